// round 6
// baseline (speedup 1.0000x reference)
#include <cuda_runtime.h>
#include <cuda_bf16.h>
#include <cstdint>

// ---------------------------------------------------------------------------
// Problem constants
// ---------------------------------------------------------------------------
#define BATCH   4
#define SEQ     2048
#define CDIM    2048
#define NHEAD   16
#define HD      128
#define QKVDIM  (3 * CDIM)    // 6144
#define MROWS   (BATCH * SEQ) // 8192

__device__ float g_qkv [(size_t)MROWS * QKVDIM];   // [8192, 6144] (tf32-rounded)
__device__ float g_y   [(size_t)MROWS * CDIM];     // [8192, 2048] (tf32-rounded)
__device__ float g_xtf [(size_t)MROWS * CDIM];     // x rounded
__device__ float g_wqkv[(size_t)CDIM * QKVDIM];    // Wqkv rounded
__device__ float g_wprj[(size_t)CDIM * CDIM];      // Wproj rounded

// ---------------------------------------------------------------------------
// Helpers
// ---------------------------------------------------------------------------
__device__ __forceinline__ void cp_async16(void* smem_dst, const void* gmem_src) {
    uint32_t s = (uint32_t)__cvta_generic_to_shared(smem_dst);
    asm volatile("cp.async.cg.shared.global [%0], [%1], 16;\n" :: "r"(s), "l"(gmem_src));
}
__device__ __forceinline__ float f2tf_f(float x) {
    float r;
    asm("cvt.rna.tf32.f32 %0, %1;" : "=f"(r) : "f"(x));
    return r;
}
__device__ __forceinline__ uint32_t f2tf(float x) {
    uint32_t r;
    asm("cvt.rna.tf32.f32 %0, %1;" : "=r"(r) : "f"(x));
    return r;
}
__device__ __forceinline__ void mma_tf32(float* d, const uint32_t* a, const uint32_t* b) {
    asm volatile(
        "mma.sync.aligned.m16n8k8.row.col.f32.tf32.tf32.f32 "
        "{%0,%1,%2,%3}, {%4,%5,%6,%7}, {%8,%9}, {%0,%1,%2,%3};"
        : "+f"(d[0]), "+f"(d[1]), "+f"(d[2]), "+f"(d[3])
        : "r"(a[0]), "r"(a[1]), "r"(a[2]), "r"(a[3]), "r"(b[0]), "r"(b[1]));
}

// ---------------------------------------------------------------------------
// Prepass: round fp32 buffer to tf32 (vectorized)
// ---------------------------------------------------------------------------
__global__ void round_tf32(const float* __restrict__ src, float* __restrict__ dst,
                           int n4)
{
    int i = blockIdx.x * blockDim.x + threadIdx.x;
    if (i < n4) {
        float4 v = ((const float4*)src)[i];
        ((float4*)dst)[i] = make_float4(f2tf_f(v.x), f2tf_f(v.y),
                                        f2tf_f(v.z), f2tf_f(v.w));
    }
}

// ---------------------------------------------------------------------------
// TF32 tensor-core GEMM — pre-rounded operands, 3-stage cp.async pipeline,
// ONE __syncthreads per BK-iteration.
// ---------------------------------------------------------------------------
#define BM 128
#define BN 128
#define BK 32
#define BKP 36
#define BNP 136

#define SMEM_A_FLOATS (BM * BKP)                  // 4608
#define SMEM_B_FLOATS (BK * BNP)                  // 4352
#define SMEM_STAGE    (SMEM_A_FLOATS + SMEM_B_FLOATS)
#define GEMM_STAGES   3
#define GEMM_SMEM_BYTES (GEMM_STAGES * SMEM_STAGE * 4)   // 107,520 B

template<bool ROUND_C>
__global__ __launch_bounds__(256, 2)
void gemm_tf32(const float* __restrict__ A, const float* __restrict__ B,
               float* __restrict__ C, int M, int N, int K)
{
    extern __shared__ float sm[];

    const int tid  = threadIdx.x;
    const int lane = tid & 31;
    const int warp = tid >> 5;
    const int g    = lane >> 2;
    const int tig  = lane & 3;
    const int Wm   = (warp >> 1) * 32;
    const int Wn   = (warp & 1) * 64;
    const int brow = blockIdx.y * BM;
    const int bcol = blockIdx.x * BN;

    float acc[2][8][4];
    #pragma unroll
    for (int mt = 0; mt < 2; ++mt)
        #pragma unroll
        for (int nt = 0; nt < 8; ++nt)
            #pragma unroll
            for (int j = 0; j < 4; ++j) acc[mt][nt][j] = 0.0f;

    auto load_tile = [&](int k0, int buf) {
        float* a_s = sm + buf * SMEM_STAGE;
        float* b_s = a_s + SMEM_A_FLOATS;
        #pragma unroll
        for (int q = 0; q < 4; ++q) {
            int idx = tid + q * 256;
            int r = idx >> 3;
            int c = (idx & 7) * 4;
            cp_async16(a_s + r * BKP + c, A + (size_t)(brow + r) * K + k0 + c);
        }
        #pragma unroll
        for (int q = 0; q < 4; ++q) {
            int idx = tid + q * 256;
            int r = idx >> 5;
            int c = (idx & 31) * 4;
            cp_async16(b_s + r * BNP + c, B + (size_t)(k0 + r) * N + bcol + c);
        }
        asm volatile("cp.async.commit_group;\n");
    };

    const int nIter = K / BK;
    load_tile(0, 0);
    load_tile(BK, 1);

    int buf = 0, buf2 = 2;   // buf: read this iter; buf2: write target (it+2)
    for (int it = 0; it < nIter; ++it) {
        if (it + 1 < nIter) {
            asm volatile("cp.async.wait_group 1;\n");
        } else {
            asm volatile("cp.async.wait_group 0;\n");
        }
        __syncthreads();   // loads for `it` visible to all; all warps done with it-1

        if (it + 2 < nIter)
            load_tile((it + 2) * BK, buf2);   // buf2 == buffer read at it-1: safe

        const float* a_s = sm + buf * SMEM_STAGE;
        const float* b_s = a_s + SMEM_A_FLOATS;

        #pragma unroll
        for (int ks = 0; ks < 4; ++ks) {
            uint32_t af[2][4], bf[8][2];
            #pragma unroll
            for (int mt = 0; mt < 2; ++mt) {
                const float* p = a_s + (size_t)(Wm + mt * 16 + g) * BKP + ks * 8 + tig;
                af[mt][0] = __float_as_uint(p[0]);
                af[mt][1] = __float_as_uint(p[8 * BKP]);
                af[mt][2] = __float_as_uint(p[4]);
                af[mt][3] = __float_as_uint(p[8 * BKP + 4]);
            }
            #pragma unroll
            for (int nt = 0; nt < 8; ++nt) {
                const float* p = b_s + (size_t)(ks * 8 + tig) * BNP + Wn + nt * 8 + g;
                bf[nt][0] = __float_as_uint(p[0]);
                bf[nt][1] = __float_as_uint(p[4 * BNP]);
            }
            #pragma unroll
            for (int mt = 0; mt < 2; ++mt)
                #pragma unroll
                for (int nt = 0; nt < 8; ++nt)
                    mma_tf32(acc[mt][nt], af[mt], bf[nt]);
        }

        buf  = (buf  == GEMM_STAGES - 1) ? 0 : buf  + 1;
        buf2 = (buf2 == GEMM_STAGES - 1) ? 0 : buf2 + 1;
    }

    #pragma unroll
    for (int mt = 0; mt < 2; ++mt) {
        int row = brow + Wm + mt * 16 + g;
        #pragma unroll
        for (int nt = 0; nt < 8; ++nt) {
            int col = bcol + Wn + nt * 8 + tig * 2;
            float v0 = acc[mt][nt][0], v1 = acc[mt][nt][1];
            float v2 = acc[mt][nt][2], v3 = acc[mt][nt][3];
            if (ROUND_C) {
                v0 = f2tf_f(v0); v1 = f2tf_f(v1);
                v2 = f2tf_f(v2); v3 = f2tf_f(v3);
            }
            *(float2*)(C + (size_t)row * N + col) = make_float2(v0, v1);
            *(float2*)(C + (size_t)(row + 8) * N + col) = make_float2(v2, v3);
        }
    }
}

// ---------------------------------------------------------------------------
// Tensor-core flash attention (tf32 mma, causal), cp.async double-buffered K/V.
// (unchanged from R5 — measured good; isolating the GEMM delta this round)
// ---------------------------------------------------------------------------
#define ABQ 128
#define ABK 64
#define KP  132
#define VP  136
#define PP  68
#define SKV (ABK * KP + ABK * VP)

#define ATTN_SMEM_FLOATS (2 * SKV + ABQ * PP)
#define ATTN_SMEM_BYTES  (ATTN_SMEM_FLOATS * 4)   // 172 KB

__global__ __launch_bounds__(256, 1)
void attn_tc(const float* __restrict__ qkv, float* __restrict__ y)
{
    extern __shared__ float sm[];
    float* Ps = sm + 2 * SKV;

    const int tid  = threadIdx.x;
    const int lane = tid & 31;
    const int warp = tid >> 5;
    const int g    = lane >> 2;
    const int tig  = lane & 3;
    const int qt   = (int)gridDim.x - 1 - (int)blockIdx.x;
    const int h    = blockIdx.y;
    const int b    = blockIdx.z;

    const size_t base  = (size_t)b * SEQ * QKVDIM + (size_t)h * HD;
    const float  scale = 0.08838834764831845f;
    const int    r0    = warp * 16;

    uint32_t qf[16][4];
    {
        float* QST = sm;
        for (int i = tid; i < ABQ * 32; i += 256) {
            int r = i >> 5, c4 = (i & 31) * 4;
            float4 v = *(const float4*)(qkv + base + (size_t)(qt * ABQ + r) * QKVDIM + c4);
            *(float4*)(QST + r * KP + c4) = v;
        }
        __syncthreads();
        #pragma unroll
        for (int ks = 0; ks < 16; ++ks) {
            int c = ks * 8 + tig;
            qf[ks][0] = f2tf(QST[(r0 + g)     * KP + c]     * scale);
            qf[ks][1] = f2tf(QST[(r0 + g + 8) * KP + c]     * scale);
            qf[ks][2] = f2tf(QST[(r0 + g)     * KP + c + 4] * scale);
            qf[ks][3] = f2tf(QST[(r0 + g + 8) * KP + c + 4] * scale);
        }
        __syncthreads();
    }

    float of[16][4];
    #pragma unroll
    for (int nb = 0; nb < 16; ++nb)
        #pragma unroll
        for (int j = 0; j < 4; ++j) of[nb][j] = 0.0f;

    float m0 = -1e30f, m1 = -1e30f, l0 = 0.0f, l1 = 0.0f;
    const int rowg0  = qt * ABQ + r0 + g;
    const int rowg1  = rowg0 + 8;
    const int rowmax = qt * ABQ + r0 + 15;
    const int ktmax  = 2 * qt + 1;

    auto load_kv = [&](int kt, int buf) {
        float* Kd = sm + buf * SKV;
        float* Vd = Kd + ABK * KP;
        #pragma unroll
        for (int q = 0; q < 8; ++q) {
            int i = tid + q * 256;
            int r = i >> 5, c4 = (i & 31) * 4;
            size_t tok = (size_t)(kt * ABK + r) * QKVDIM;
            cp_async16(Kd + r * KP + c4, qkv + base + CDIM     + tok + c4);
            cp_async16(Vd + r * VP + c4, qkv + base + 2 * CDIM + tok + c4);
        }
        asm volatile("cp.async.commit_group;\n");
    };

    load_kv(0, 0);

    for (int kt = 0; kt <= ktmax; ++kt) {
        if (kt + 1 <= ktmax) {
            load_kv(kt + 1, (kt + 1) & 1);
            asm volatile("cp.async.wait_group 1;\n");
        } else {
            asm volatile("cp.async.wait_group 0;\n");
        }
        __syncthreads();

        const float* Ks = sm + (kt & 1) * SKV;
        const float* Vs = Ks + ABK * KP;

        const int colbase = kt * ABK;
        const bool skip = colbase > rowmax;

        if (!skip) {
            float sf[8][4];
            #pragma unroll
            for (int nb = 0; nb < 8; ++nb)
                #pragma unroll
                for (int j = 0; j < 4; ++j) sf[nb][j] = 0.0f;

            #pragma unroll
            for (int ks = 0; ks < 16; ++ks) {
                uint32_t bf[8][2];
                #pragma unroll
                for (int nb = 0; nb < 8; ++nb) {
                    const float* p = Ks + (nb * 8 + g) * KP + ks * 8 + tig;
                    bf[nb][0] = __float_as_uint(p[0]);
                    bf[nb][1] = __float_as_uint(p[4]);
                }
                #pragma unroll
                for (int nb = 0; nb < 8; ++nb)
                    mma_tf32(sf[nb], qf[ks], bf[nb]);
            }

            if (colbase + ABK - 1 > rowg0) {
                #pragma unroll
                for (int nb = 0; nb < 8; ++nb) {
                    int col = colbase + nb * 8 + 2 * tig;
                    if (col     > rowg0) sf[nb][0] = -1e30f;
                    if (col + 1 > rowg0) sf[nb][1] = -1e30f;
                    if (col     > rowg1) sf[nb][2] = -1e30f;
                    if (col + 1 > rowg1) sf[nb][3] = -1e30f;
                }
            }

            float mx0 = -1e30f, mx1 = -1e30f;
            #pragma unroll
            for (int nb = 0; nb < 8; ++nb) {
                mx0 = fmaxf(mx0, fmaxf(sf[nb][0], sf[nb][1]));
                mx1 = fmaxf(mx1, fmaxf(sf[nb][2], sf[nb][3]));
            }
            mx0 = fmaxf(mx0, __shfl_xor_sync(0xffffffffu, mx0, 1));
            mx0 = fmaxf(mx0, __shfl_xor_sync(0xffffffffu, mx0, 2));
            mx1 = fmaxf(mx1, __shfl_xor_sync(0xffffffffu, mx1, 1));
            mx1 = fmaxf(mx1, __shfl_xor_sync(0xffffffffu, mx1, 2));

            float nm0 = fmaxf(m0, mx0);
            float nm1 = fmaxf(m1, mx1);
            float cr0 = __expf(m0 - nm0);
            float cr1 = __expf(m1 - nm1);

            float rs0 = 0.0f, rs1 = 0.0f;
            #pragma unroll
            for (int nb = 0; nb < 8; ++nb) {
                float e0 = __expf(sf[nb][0] - nm0);
                float e1 = __expf(sf[nb][1] - nm0);
                float e2 = __expf(sf[nb][2] - nm1);
                float e3 = __expf(sf[nb][3] - nm1);
                rs0 += e0 + e1;
                rs1 += e2 + e3;
                *(float2*)(Ps + (r0 + g)     * PP + nb * 8 + 2 * tig) =
                    make_float2(f2tf_f(e0), f2tf_f(e1));
                *(float2*)(Ps + (r0 + g + 8) * PP + nb * 8 + 2 * tig) =
                    make_float2(f2tf_f(e2), f2tf_f(e3));
            }
            rs0 += __shfl_xor_sync(0xffffffffu, rs0, 1);
            rs0 += __shfl_xor_sync(0xffffffffu, rs0, 2);
            rs1 += __shfl_xor_sync(0xffffffffu, rs1, 1);
            rs1 += __shfl_xor_sync(0xffffffffu, rs1, 2);

            m0 = nm0; m1 = nm1;
            l0 = l0 * cr0 + rs0;
            l1 = l1 * cr1 + rs1;

            #pragma unroll
            for (int nb = 0; nb < 16; ++nb) {
                of[nb][0] *= cr0; of[nb][1] *= cr0;
                of[nb][2] *= cr1; of[nb][3] *= cr1;
            }
            __syncwarp();

            #pragma unroll
            for (int ks2 = 0; ks2 < 8; ++ks2) {
                uint32_t pa[4];
                pa[0] = __float_as_uint(Ps[(r0 + g)     * PP + ks2 * 8 + tig]);
                pa[1] = __float_as_uint(Ps[(r0 + g + 8) * PP + ks2 * 8 + tig]);
                pa[2] = __float_as_uint(Ps[(r0 + g)     * PP + ks2 * 8 + tig + 4]);
                pa[3] = __float_as_uint(Ps[(r0 + g + 8) * PP + ks2 * 8 + tig + 4]);
                #pragma unroll
                for (int nb = 0; nb < 16; ++nb) {
                    uint32_t vb[2];
                    vb[0] = __float_as_uint(Vs[(ks2 * 8 + tig)     * VP + nb * 8 + g]);
                    vb[1] = __float_as_uint(Vs[(ks2 * 8 + tig + 4) * VP + nb * 8 + g]);
                    mma_tf32(of[nb], pa, vb);
                }
            }
            __syncwarp();
        }
        __syncthreads();
    }

    float inv0 = 1.0f / l0;
    float inv1 = 1.0f / l1;
    size_t yrow0 = (size_t)b * SEQ + rowg0;
    size_t yrow1 = (size_t)b * SEQ + rowg1;
    #pragma unroll
    for (int nb = 0; nb < 16; ++nb) {
        int col = h * HD + nb * 8 + 2 * tig;
        *(float2*)(y + yrow0 * CDIM + col) =
            make_float2(f2tf_f(of[nb][0] * inv0), f2tf_f(of[nb][1] * inv0));
        *(float2*)(y + yrow1 * CDIM + col) =
            make_float2(f2tf_f(of[nb][2] * inv1), f2tf_f(of[nb][3] * inv1));
    }
}

// ---------------------------------------------------------------------------
// kernel_launch
// ---------------------------------------------------------------------------
extern "C" void kernel_launch(void* const* d_in, const int* in_sizes, int n_in,
                              void* d_out, int out_size)
{
    const float* x     = (const float*)d_in[0];
    const float* Wqkv  = (const float*)d_in[1];
    const float* Wproj = (const float*)d_in[2];
    float* out = (float*)d_out;

    float *qkv, *y, *xtf, *wqkv, *wprj;
    cudaGetSymbolAddress((void**)&qkv,  g_qkv);
    cudaGetSymbolAddress((void**)&y,    g_y);
    cudaGetSymbolAddress((void**)&xtf,  g_xtf);
    cudaGetSymbolAddress((void**)&wqkv, g_wqkv);
    cudaGetSymbolAddress((void**)&wprj, g_wprj);

    cudaFuncSetAttribute(gemm_tf32<true>,
                         cudaFuncAttributeMaxDynamicSharedMemorySize,
                         GEMM_SMEM_BYTES);
    cudaFuncSetAttribute(gemm_tf32<false>,
                         cudaFuncAttributeMaxDynamicSharedMemorySize,
                         GEMM_SMEM_BYTES);
    cudaFuncSetAttribute(attn_tc,
                         cudaFuncAttributeMaxDynamicSharedMemorySize,
                         ATTN_SMEM_BYTES);

    // 0) round inputs to tf32 once
    {
        int n4x = MROWS * CDIM / 4;
        int n4q = CDIM * QKVDIM / 4;
        int n4p = CDIM * CDIM / 4;
        round_tf32<<<(n4x + 255) / 256, 256>>>(x,     xtf,  n4x);
        round_tf32<<<(n4q + 255) / 256, 256>>>(Wqkv,  wqkv, n4q);
        round_tf32<<<(n4p + 255) / 256, 256>>>(Wproj, wprj, n4p);
    }

    // 1) qkv = x @ Wqkv  (output tf32-rounded for attention)
    gemm_tf32<true><<<dim3(QKVDIM / BN, MROWS / BM), 256, GEMM_SMEM_BYTES>>>(
        xtf, wqkv, qkv, MROWS, QKVDIM, CDIM);

    // 2) attention -> y (tf32-rounded)
    attn_tc<<<dim3(SEQ / ABQ, NHEAD, BATCH), 256, ATTN_SMEM_BYTES>>>(qkv, y);

    // 3) out = y @ Wproj (full fp32 output)
    gemm_tf32<false><<<dim3(CDIM / BN, MROWS / BM), 256, GEMM_SMEM_BYTES>>>(
        y, wprj, out, MROWS, CDIM, CDIM);
}

// round 8
// speedup vs baseline: 1.3667x; 1.3667x over previous
#include <cuda_runtime.h>
#include <cuda_bf16.h>
#include <cstdint>

// ---------------------------------------------------------------------------
// Problem constants
// ---------------------------------------------------------------------------
#define BATCH   4
#define SEQ     2048
#define CDIM    2048
#define NHEAD   16
#define HD      128
#define QKVDIM  (3 * CDIM)    // 6144
#define MROWS   (BATCH * SEQ) // 8192

__device__ float g_qkv [(size_t)MROWS * QKVDIM];   // [8192, 6144] (tf32-rounded)
__device__ float g_y   [(size_t)MROWS * CDIM];     // [8192, 2048] (tf32-rounded)
__device__ float g_xtf [(size_t)MROWS * CDIM];     // x rounded
__device__ float g_wqkv[(size_t)CDIM * QKVDIM];    // Wqkv rounded
__device__ float g_wprj[(size_t)CDIM * CDIM];      // Wproj rounded

// ---------------------------------------------------------------------------
// Helpers
// ---------------------------------------------------------------------------
__device__ __forceinline__ void cp_async16(void* smem_dst, const void* gmem_src) {
    uint32_t s = (uint32_t)__cvta_generic_to_shared(smem_dst);
    asm volatile("cp.async.cg.shared.global [%0], [%1], 16;\n" :: "r"(s), "l"(gmem_src));
}
__device__ __forceinline__ float f2tf_f(float x) {
    float r;
    asm("cvt.rna.tf32.f32 %0, %1;" : "=f"(r) : "f"(x));
    return r;
}
__device__ __forceinline__ uint32_t f2tf(float x) {
    uint32_t r;
    asm("cvt.rna.tf32.f32 %0, %1;" : "=r"(r) : "f"(x));
    return r;
}
__device__ __forceinline__ void mma_tf32(float* d, const uint32_t* a, const uint32_t* b) {
    asm volatile(
        "mma.sync.aligned.m16n8k8.row.col.f32.tf32.tf32.f32 "
        "{%0,%1,%2,%3}, {%4,%5,%6,%7}, {%8,%9}, {%0,%1,%2,%3};"
        : "+f"(d[0]), "+f"(d[1]), "+f"(d[2]), "+f"(d[3])
        : "r"(a[0]), "r"(a[1]), "r"(a[2]), "r"(a[3]), "r"(b[0]), "r"(b[1]));
}

// ---------------------------------------------------------------------------
// Prepass: round fp32 buffer to tf32 (vectorized)
// ---------------------------------------------------------------------------
__global__ void round_tf32(const float* __restrict__ src, float* __restrict__ dst,
                           int n4)
{
    int i = blockIdx.x * blockDim.x + threadIdx.x;
    if (i < n4) {
        float4 v = ((const float4*)src)[i];
        ((float4*)dst)[i] = make_float4(f2tf_f(v.x), f2tf_f(v.y),
                                        f2tf_f(v.z), f2tf_f(v.w));
    }
}

// ---------------------------------------------------------------------------
// TF32 tensor-core GEMM — pre-rounded operands, 2-stage cp.async.
// ONE 512-thread CTA per SM, 256x128 block tile, warp tile 64x32.
// Bigger tile amortizes the per-iter sync epoch over 2x MMA work.
// ---------------------------------------------------------------------------
#define BM 256
#define BN 128
#define BK 32
#define BKP 36
#define BNP 136

#define SMEM_A_FLOATS (BM * BKP)                  // 9216
#define SMEM_B_FLOATS (BK * BNP)                  // 4352
#define SMEM_STAGE    (SMEM_A_FLOATS + SMEM_B_FLOATS)   // 13568 floats
#define GEMM_SMEM_BYTES (2 * SMEM_STAGE * 4)      // 108,544 B

template<bool ROUND_C>
__global__ __launch_bounds__(512, 1)
void gemm_tf32(const float* __restrict__ A, const float* __restrict__ B,
               float* __restrict__ C, int M, int N, int K)
{
    extern __shared__ float sm[];

    const int tid  = threadIdx.x;
    const int lane = tid & 31;
    const int warp = tid >> 5;          // 0..15
    const int g    = lane >> 2;
    const int tig  = lane & 3;
    const int Wm   = (warp >> 2) * 64;  // 4 warp-rows of 64
    const int Wn   = (warp & 3) * 32;   // 4 warp-cols of 32
    const int brow = blockIdx.y * BM;
    const int bcol = blockIdx.x * BN;

    float acc[4][4][4];
    #pragma unroll
    for (int mt = 0; mt < 4; ++mt)
        #pragma unroll
        for (int nt = 0; nt < 4; ++nt)
            #pragma unroll
            for (int j = 0; j < 4; ++j) acc[mt][nt][j] = 0.0f;

    auto load_tile = [&](int k0, int buf) {
        float* a_s = sm + buf * SMEM_STAGE;
        float* b_s = a_s + SMEM_A_FLOATS;
        #pragma unroll
        for (int q = 0; q < 4; ++q) {
            int idx = tid + q * 512;          // 0..2047
            int r = idx >> 3;                 // 0..255
            int c = (idx & 7) * 4;            // 0..28
            cp_async16(a_s + r * BKP + c, A + (size_t)(brow + r) * K + k0 + c);
        }
        #pragma unroll
        for (int q = 0; q < 2; ++q) {
            int idx = tid + q * 512;          // 0..1023
            int r = idx >> 5;                 // 0..31
            int c = (idx & 31) * 4;           // 0..124
            cp_async16(b_s + r * BNP + c, B + (size_t)(k0 + r) * N + bcol + c);
        }
        asm volatile("cp.async.commit_group;\n");
    };

    const int nIter = K / BK;
    load_tile(0, 0);

    for (int it = 0; it < nIter; ++it) {
        if (it + 1 < nIter) {
            load_tile((it + 1) * BK, (it + 1) & 1);
            asm volatile("cp.async.wait_group 1;\n");
        } else {
            asm volatile("cp.async.wait_group 0;\n");
        }
        __syncthreads();

        const float* a_s = sm + (it & 1) * SMEM_STAGE;
        const float* b_s = a_s + SMEM_A_FLOATS;

        #pragma unroll
        for (int ks = 0; ks < 4; ++ks) {
            uint32_t af[4][4], bf[4][2];
            #pragma unroll
            for (int mt = 0; mt < 4; ++mt) {
                const float* p = a_s + (size_t)(Wm + mt * 16 + g) * BKP + ks * 8 + tig;
                af[mt][0] = __float_as_uint(p[0]);
                af[mt][1] = __float_as_uint(p[8 * BKP]);
                af[mt][2] = __float_as_uint(p[4]);
                af[mt][3] = __float_as_uint(p[8 * BKP + 4]);
            }
            #pragma unroll
            for (int nt = 0; nt < 4; ++nt) {
                const float* p = b_s + (size_t)(ks * 8 + tig) * BNP + Wn + nt * 8 + g;
                bf[nt][0] = __float_as_uint(p[0]);
                bf[nt][1] = __float_as_uint(p[4 * BNP]);
            }
            #pragma unroll
            for (int mt = 0; mt < 4; ++mt)
                #pragma unroll
                for (int nt = 0; nt < 4; ++nt)
                    mma_tf32(acc[mt][nt], af[mt], bf[nt]);
        }
        __syncthreads();
    }

    #pragma unroll
    for (int mt = 0; mt < 4; ++mt) {
        int row = brow + Wm + mt * 16 + g;
        #pragma unroll
        for (int nt = 0; nt < 4; ++nt) {
            int col = bcol + Wn + nt * 8 + tig * 2;
            float v0 = acc[mt][nt][0], v1 = acc[mt][nt][1];
            float v2 = acc[mt][nt][2], v3 = acc[mt][nt][3];
            if (ROUND_C) {
                v0 = f2tf_f(v0); v1 = f2tf_f(v1);
                v2 = f2tf_f(v2); v3 = f2tf_f(v3);
            }
            *(float2*)(C + (size_t)row * N + col) = make_float2(v0, v1);
            *(float2*)(C + (size_t)(row + 8) * N + col) = make_float2(v2, v3);
        }
    }
}

// ---------------------------------------------------------------------------
// Tensor-core flash attention (tf32 mma, causal), cp.async double-buffered K/V.
// (unchanged from R5 best)
// ---------------------------------------------------------------------------
#define ABQ 128
#define ABK 64
#define KP  132
#define VP  136
#define PP  68
#define SKV (ABK * KP + ABK * VP)

#define ATTN_SMEM_FLOATS (2 * SKV + ABQ * PP)
#define ATTN_SMEM_BYTES  (ATTN_SMEM_FLOATS * 4)   // 172 KB

__global__ __launch_bounds__(256, 1)
void attn_tc(const float* __restrict__ qkv, float* __restrict__ y)
{
    extern __shared__ float sm[];
    float* Ps = sm + 2 * SKV;

    const int tid  = threadIdx.x;
    const int lane = tid & 31;
    const int warp = tid >> 5;
    const int g    = lane >> 2;
    const int tig  = lane & 3;
    const int qt   = (int)gridDim.x - 1 - (int)blockIdx.x;
    const int h    = blockIdx.y;
    const int b    = blockIdx.z;

    const size_t base  = (size_t)b * SEQ * QKVDIM + (size_t)h * HD;
    const float  scale = 0.08838834764831845f;
    const int    r0    = warp * 16;

    uint32_t qf[16][4];
    {
        float* QST = sm;
        for (int i = tid; i < ABQ * 32; i += 256) {
            int r = i >> 5, c4 = (i & 31) * 4;
            float4 v = *(const float4*)(qkv + base + (size_t)(qt * ABQ + r) * QKVDIM + c4);
            *(float4*)(QST + r * KP + c4) = v;
        }
        __syncthreads();
        #pragma unroll
        for (int ks = 0; ks < 16; ++ks) {
            int c = ks * 8 + tig;
            qf[ks][0] = f2tf(QST[(r0 + g)     * KP + c]     * scale);
            qf[ks][1] = f2tf(QST[(r0 + g + 8) * KP + c]     * scale);
            qf[ks][2] = f2tf(QST[(r0 + g)     * KP + c + 4] * scale);
            qf[ks][3] = f2tf(QST[(r0 + g + 8) * KP + c + 4] * scale);
        }
        __syncthreads();
    }

    float of[16][4];
    #pragma unroll
    for (int nb = 0; nb < 16; ++nb)
        #pragma unroll
        for (int j = 0; j < 4; ++j) of[nb][j] = 0.0f;

    float m0 = -1e30f, m1 = -1e30f, l0 = 0.0f, l1 = 0.0f;
    const int rowg0  = qt * ABQ + r0 + g;
    const int rowg1  = rowg0 + 8;
    const int rowmax = qt * ABQ + r0 + 15;
    const int ktmax  = 2 * qt + 1;

    auto load_kv = [&](int kt, int buf) {
        float* Kd = sm + buf * SKV;
        float* Vd = Kd + ABK * KP;
        #pragma unroll
        for (int q = 0; q < 8; ++q) {
            int i = tid + q * 256;
            int r = i >> 5, c4 = (i & 31) * 4;
            size_t tok = (size_t)(kt * ABK + r) * QKVDIM;
            cp_async16(Kd + r * KP + c4, qkv + base + CDIM     + tok + c4);
            cp_async16(Vd + r * VP + c4, qkv + base + 2 * CDIM + tok + c4);
        }
        asm volatile("cp.async.commit_group;\n");
    };

    load_kv(0, 0);

    for (int kt = 0; kt <= ktmax; ++kt) {
        if (kt + 1 <= ktmax) {
            load_kv(kt + 1, (kt + 1) & 1);
            asm volatile("cp.async.wait_group 1;\n");
        } else {
            asm volatile("cp.async.wait_group 0;\n");
        }
        __syncthreads();

        const float* Ks = sm + (kt & 1) * SKV;
        const float* Vs = Ks + ABK * KP;

        const int colbase = kt * ABK;
        const bool skip = colbase > rowmax;

        if (!skip) {
            float sf[8][4];
            #pragma unroll
            for (int nb = 0; nb < 8; ++nb)
                #pragma unroll
                for (int j = 0; j < 4; ++j) sf[nb][j] = 0.0f;

            #pragma unroll
            for (int ks = 0; ks < 16; ++ks) {
                uint32_t bf[8][2];
                #pragma unroll
                for (int nb = 0; nb < 8; ++nb) {
                    const float* p = Ks + (nb * 8 + g) * KP + ks * 8 + tig;
                    bf[nb][0] = __float_as_uint(p[0]);
                    bf[nb][1] = __float_as_uint(p[4]);
                }
                #pragma unroll
                for (int nb = 0; nb < 8; ++nb)
                    mma_tf32(sf[nb], qf[ks], bf[nb]);
            }

            if (colbase + ABK - 1 > rowg0) {
                #pragma unroll
                for (int nb = 0; nb < 8; ++nb) {
                    int col = colbase + nb * 8 + 2 * tig;
                    if (col     > rowg0) sf[nb][0] = -1e30f;
                    if (col + 1 > rowg0) sf[nb][1] = -1e30f;
                    if (col     > rowg1) sf[nb][2] = -1e30f;
                    if (col + 1 > rowg1) sf[nb][3] = -1e30f;
                }
            }

            float mx0 = -1e30f, mx1 = -1e30f;
            #pragma unroll
            for (int nb = 0; nb < 8; ++nb) {
                mx0 = fmaxf(mx0, fmaxf(sf[nb][0], sf[nb][1]));
                mx1 = fmaxf(mx1, fmaxf(sf[nb][2], sf[nb][3]));
            }
            mx0 = fmaxf(mx0, __shfl_xor_sync(0xffffffffu, mx0, 1));
            mx0 = fmaxf(mx0, __shfl_xor_sync(0xffffffffu, mx0, 2));
            mx1 = fmaxf(mx1, __shfl_xor_sync(0xffffffffu, mx1, 1));
            mx1 = fmaxf(mx1, __shfl_xor_sync(0xffffffffu, mx1, 2));

            float nm0 = fmaxf(m0, mx0);
            float nm1 = fmaxf(m1, mx1);
            float cr0 = __expf(m0 - nm0);
            float cr1 = __expf(m1 - nm1);

            float rs0 = 0.0f, rs1 = 0.0f;
            #pragma unroll
            for (int nb = 0; nb < 8; ++nb) {
                float e0 = __expf(sf[nb][0] - nm0);
                float e1 = __expf(sf[nb][1] - nm0);
                float e2 = __expf(sf[nb][2] - nm1);
                float e3 = __expf(sf[nb][3] - nm1);
                rs0 += e0 + e1;
                rs1 += e2 + e3;
                *(float2*)(Ps + (r0 + g)     * PP + nb * 8 + 2 * tig) =
                    make_float2(f2tf_f(e0), f2tf_f(e1));
                *(float2*)(Ps + (r0 + g + 8) * PP + nb * 8 + 2 * tig) =
                    make_float2(f2tf_f(e2), f2tf_f(e3));
            }
            rs0 += __shfl_xor_sync(0xffffffffu, rs0, 1);
            rs0 += __shfl_xor_sync(0xffffffffu, rs0, 2);
            rs1 += __shfl_xor_sync(0xffffffffu, rs1, 1);
            rs1 += __shfl_xor_sync(0xffffffffu, rs1, 2);

            m0 = nm0; m1 = nm1;
            l0 = l0 * cr0 + rs0;
            l1 = l1 * cr1 + rs1;

            #pragma unroll
            for (int nb = 0; nb < 16; ++nb) {
                of[nb][0] *= cr0; of[nb][1] *= cr0;
                of[nb][2] *= cr1; of[nb][3] *= cr1;
            }
            __syncwarp();

            #pragma unroll
            for (int ks2 = 0; ks2 < 8; ++ks2) {
                uint32_t pa[4];
                pa[0] = __float_as_uint(Ps[(r0 + g)     * PP + ks2 * 8 + tig]);
                pa[1] = __float_as_uint(Ps[(r0 + g + 8) * PP + ks2 * 8 + tig]);
                pa[2] = __float_as_uint(Ps[(r0 + g)     * PP + ks2 * 8 + tig + 4]);
                pa[3] = __float_as_uint(Ps[(r0 + g + 8) * PP + ks2 * 8 + tig + 4]);
                #pragma unroll
                for (int nb = 0; nb < 16; ++nb) {
                    uint32_t vb[2];
                    vb[0] = __float_as_uint(Vs[(ks2 * 8 + tig)     * VP + nb * 8 + g]);
                    vb[1] = __float_as_uint(Vs[(ks2 * 8 + tig + 4) * VP + nb * 8 + g]);
                    mma_tf32(of[nb], pa, vb);
                }
            }
            __syncwarp();
        }
        __syncthreads();
    }

    float inv0 = 1.0f / l0;
    float inv1 = 1.0f / l1;
    size_t yrow0 = (size_t)b * SEQ + rowg0;
    size_t yrow1 = (size_t)b * SEQ + rowg1;
    #pragma unroll
    for (int nb = 0; nb < 16; ++nb) {
        int col = h * HD + nb * 8 + 2 * tig;
        *(float2*)(y + yrow0 * CDIM + col) =
            make_float2(f2tf_f(of[nb][0] * inv0), f2tf_f(of[nb][1] * inv0));
        *(float2*)(y + yrow1 * CDIM + col) =
            make_float2(f2tf_f(of[nb][2] * inv1), f2tf_f(of[nb][3] * inv1));
    }
}

// ---------------------------------------------------------------------------
// kernel_launch
// ---------------------------------------------------------------------------
extern "C" void kernel_launch(void* const* d_in, const int* in_sizes, int n_in,
                              void* d_out, int out_size)
{
    const float* x     = (const float*)d_in[0];
    const float* Wqkv  = (const float*)d_in[1];
    const float* Wproj = (const float*)d_in[2];
    float* out = (float*)d_out;

    float *qkv, *y, *xtf, *wqkv, *wprj;
    cudaGetSymbolAddress((void**)&qkv,  g_qkv);
    cudaGetSymbolAddress((void**)&y,    g_y);
    cudaGetSymbolAddress((void**)&xtf,  g_xtf);
    cudaGetSymbolAddress((void**)&wqkv, g_wqkv);
    cudaGetSymbolAddress((void**)&wprj, g_wprj);

    cudaFuncSetAttribute(gemm_tf32<true>,
                         cudaFuncAttributeMaxDynamicSharedMemorySize,
                         GEMM_SMEM_BYTES);
    cudaFuncSetAttribute(gemm_tf32<false>,
                         cudaFuncAttributeMaxDynamicSharedMemorySize,
                         GEMM_SMEM_BYTES);
    cudaFuncSetAttribute(attn_tc,
                         cudaFuncAttributeMaxDynamicSharedMemorySize,
                         ATTN_SMEM_BYTES);

    // 0) round inputs to tf32 once
    {
        int n4x = MROWS * CDIM / 4;
        int n4q = CDIM * QKVDIM / 4;
        int n4p = CDIM * CDIM / 4;
        round_tf32<<<(n4x + 255) / 256, 256>>>(x,     xtf,  n4x);
        round_tf32<<<(n4q + 255) / 256, 256>>>(Wqkv,  wqkv, n4q);
        round_tf32<<<(n4p + 255) / 256, 256>>>(Wproj, wprj, n4p);
    }

    // 1) qkv = x @ Wqkv  (output tf32-rounded for attention)
    gemm_tf32<true><<<dim3(QKVDIM / BN, MROWS / BM), 512, GEMM_SMEM_BYTES>>>(
        xtf, wqkv, qkv, MROWS, QKVDIM, CDIM);

    // 2) attention -> y (tf32-rounded)
    attn_tc<<<dim3(SEQ / ABQ, NHEAD, BATCH), 256, ATTN_SMEM_BYTES>>>(qkv, y);

    // 3) out = y @ Wproj (full fp32 output)
    gemm_tf32<false><<<dim3(CDIM / BN, MROWS / BM), 512, GEMM_SMEM_BYTES>>>(
        y, wprj, out, MROWS, CDIM, CDIM);
}

// round 9
// speedup vs baseline: 2.3269x; 1.7025x over previous
#include <cuda_runtime.h>
#include <cuda_fp16.h>
#include <cuda_bf16.h>
#include <cstdint>

// ---------------------------------------------------------------------------
// Problem constants
// ---------------------------------------------------------------------------
#define BATCH   4
#define SEQ     2048
#define CDIM    2048
#define NHEAD   16
#define HD      128
#define QKVDIM  (3 * CDIM)    // 6144
#define MROWS   (BATCH * SEQ) // 8192

__device__ float  g_qkv [(size_t)MROWS * QKVDIM];    // fp32, tf32-rounded (attention input)
__device__ __half g_yh  [(size_t)MROWS * CDIM];      // attention output, fp16
__device__ __half g_xh  [(size_t)MROWS * CDIM];      // x in fp16
__device__ __half g_wqkvT[(size_t)QKVDIM * CDIM];    // Wqkv^T fp16  [6144][2048]
__device__ __half g_wprjT[(size_t)CDIM * CDIM];      // Wproj^T fp16 [2048][2048]

// ---------------------------------------------------------------------------
// Helpers
// ---------------------------------------------------------------------------
__device__ __forceinline__ void cp_async16(void* smem_dst, const void* gmem_src) {
    uint32_t s = (uint32_t)__cvta_generic_to_shared(smem_dst);
    asm volatile("cp.async.cg.shared.global [%0], [%1], 16;\n" :: "r"(s), "l"(gmem_src));
}
__device__ __forceinline__ float f2tf_f(float x) {
    float r;
    asm("cvt.rna.tf32.f32 %0, %1;" : "=f"(r) : "f"(x));
    return r;
}
__device__ __forceinline__ uint32_t f2tf(float x) {
    uint32_t r;
    asm("cvt.rna.tf32.f32 %0, %1;" : "=r"(r) : "f"(x));
    return r;
}
__device__ __forceinline__ void mma_tf32(float* d, const uint32_t* a, const uint32_t* b) {
    asm volatile(
        "mma.sync.aligned.m16n8k8.row.col.f32.tf32.tf32.f32 "
        "{%0,%1,%2,%3}, {%4,%5,%6,%7}, {%8,%9}, {%0,%1,%2,%3};"
        : "+f"(d[0]), "+f"(d[1]), "+f"(d[2]), "+f"(d[3])
        : "r"(a[0]), "r"(a[1]), "r"(a[2]), "r"(a[3]), "r"(b[0]), "r"(b[1]));
}
__device__ __forceinline__ void mma_fp16(float* d, const uint32_t* a, const uint32_t* b) {
    asm volatile(
        "mma.sync.aligned.m16n8k16.row.col.f32.f16.f16.f32 "
        "{%0,%1,%2,%3}, {%4,%5,%6,%7}, {%8,%9}, {%0,%1,%2,%3};"
        : "+f"(d[0]), "+f"(d[1]), "+f"(d[2]), "+f"(d[3])
        : "r"(a[0]), "r"(a[1]), "r"(a[2]), "r"(a[3]), "r"(b[0]), "r"(b[1]));
}

// ---------------------------------------------------------------------------
// Prepass kernels
// ---------------------------------------------------------------------------
__global__ void to_half(const float* __restrict__ src, __half* __restrict__ dst, int n4)
{
    int i = blockIdx.x * blockDim.x + threadIdx.x;
    if (i < n4) {
        float4 v = ((const float4*)src)[i];
        __half2* d2 = (__half2*)dst + i * 2;
        d2[0] = __floats2half2_rn(v.x, v.y);
        d2[1] = __floats2half2_rn(v.z, v.w);
    }
}

// dst[N][K] (half) = src[K][N]^T ; block (32,8), grid (N/32, K/32)
__global__ void transpose_half(const float* __restrict__ src, __half* __restrict__ dst,
                               int K, int N)
{
    __shared__ float t[32][33];
    int nb = blockIdx.x * 32, kb = blockIdx.y * 32;
    int tx = threadIdx.x, ty = threadIdx.y;
    #pragma unroll
    for (int i = 0; i < 4; ++i)
        t[ty + i * 8][tx] = src[(size_t)(kb + ty + i * 8) * N + nb + tx];
    __syncthreads();
    #pragma unroll
    for (int i = 0; i < 4; ++i)
        dst[(size_t)(nb + ty + i * 8) * K + kb + tx] = __float2half(t[tx][ty + i * 8]);
}

// ---------------------------------------------------------------------------
// FP16 tensor-core GEMM: C[M,N] = A[M,K] @ BT[N,K]^T, fp32 accum.
// A, BT row-major half. 128x128 tile, BK=64 halfs, 2-stage cp.async,
// 256 thr (8 warps, warp tile 32x64), 2 CTAs/SM. All frag loads = half2 LDS.
// ---------------------------------------------------------------------------
#define BM 128
#define BN 128
#define BKH 64       // K per tile (halfs)
#define BKP 72       // padded pitch (halfs): bank = 4g+tig, conflict-free

#define SMEM_AB_HALFS (BM * BKP)                    // 9216 halfs = 18432 B
#define SMEM_STAGE_H  (2 * SMEM_AB_HALFS)           // A + B
#define GEMM_SMEM_BYTES (2 * SMEM_STAGE_H * 2)      // 73,728 B

template<bool ROUND_C>
__global__ __launch_bounds__(256, 2)
void gemm_fp16(const __half* __restrict__ A, const __half* __restrict__ BT,
               float* __restrict__ C, int M, int N, int K)
{
    extern __shared__ __half smh[];

    const int tid  = threadIdx.x;
    const int lane = tid & 31;
    const int warp = tid >> 5;
    const int g    = lane >> 2;
    const int tig  = lane & 3;
    const int Wm   = (warp >> 1) * 32;
    const int Wn   = (warp & 1) * 64;
    const int brow = blockIdx.y * BM;
    const int bcol = blockIdx.x * BN;

    float acc[2][8][4];
    #pragma unroll
    for (int mt = 0; mt < 2; ++mt)
        #pragma unroll
        for (int nt = 0; nt < 8; ++nt)
            #pragma unroll
            for (int j = 0; j < 4; ++j) acc[mt][nt][j] = 0.0f;

    // load A[128][64] and BT[128][64] tiles; 128B/row = 8 x 16B chunks
    auto load_tile = [&](int k0, int buf) {
        __half* a_s = smh + buf * SMEM_STAGE_H;
        __half* b_s = a_s + SMEM_AB_HALFS;
        #pragma unroll
        for (int q = 0; q < 4; ++q) {
            int idx = tid + q * 256;          // 0..1023
            int r = idx >> 3;                 // 0..127
            int j = idx & 7;                  // 16B chunk
            cp_async16(a_s + r * BKP + j * 8, A + (size_t)(brow + r) * K + k0 + j * 8);
        }
        #pragma unroll
        for (int q = 0; q < 4; ++q) {
            int idx = tid + q * 256;
            int r = idx >> 3;
            int j = idx & 7;
            cp_async16(b_s + r * BKP + j * 8, BT + (size_t)(bcol + r) * K + k0 + j * 8);
        }
        asm volatile("cp.async.commit_group;\n");
    };

    const int nIter = K / BKH;
    load_tile(0, 0);

    for (int it = 0; it < nIter; ++it) {
        if (it + 1 < nIter) {
            load_tile((it + 1) * BKH, (it + 1) & 1);
            asm volatile("cp.async.wait_group 1;\n");
        } else {
            asm volatile("cp.async.wait_group 0;\n");
        }
        __syncthreads();

        const __half* a_s = smh + (it & 1) * SMEM_STAGE_H;
        const __half* b_s = a_s + SMEM_AB_HALFS;

        #pragma unroll
        for (int ks = 0; ks < 4; ++ks) {       // 4 x K=16
            uint32_t af[2][4], bf[8][2];
            #pragma unroll
            for (int mt = 0; mt < 2; ++mt) {
                const __half* p = a_s + (size_t)(Wm + mt * 16 + g) * BKP + ks * 16 + 2 * tig;
                af[mt][0] = *(const uint32_t*)(p);
                af[mt][1] = *(const uint32_t*)(p + 8 * BKP);
                af[mt][2] = *(const uint32_t*)(p + 8);
                af[mt][3] = *(const uint32_t*)(p + 8 * BKP + 8);
            }
            #pragma unroll
            for (int nt = 0; nt < 8; ++nt) {
                const __half* p = b_s + (size_t)(Wn + nt * 8 + g) * BKP + ks * 16 + 2 * tig;
                bf[nt][0] = *(const uint32_t*)(p);
                bf[nt][1] = *(const uint32_t*)(p + 8);
            }
            #pragma unroll
            for (int mt = 0; mt < 2; ++mt)
                #pragma unroll
                for (int nt = 0; nt < 8; ++nt)
                    mma_fp16(acc[mt][nt], af[mt], bf[nt]);
        }
        __syncthreads();
    }

    #pragma unroll
    for (int mt = 0; mt < 2; ++mt) {
        int row = brow + Wm + mt * 16 + g;
        #pragma unroll
        for (int nt = 0; nt < 8; ++nt) {
            int col = bcol + Wn + nt * 8 + tig * 2;
            float v0 = acc[mt][nt][0], v1 = acc[mt][nt][1];
            float v2 = acc[mt][nt][2], v3 = acc[mt][nt][3];
            if (ROUND_C) {
                v0 = f2tf_f(v0); v1 = f2tf_f(v1);
                v2 = f2tf_f(v2); v3 = f2tf_f(v3);
            }
            *(float2*)(C + (size_t)row * N + col) = make_float2(v0, v1);
            *(float2*)(C + (size_t)(row + 8) * N + col) = make_float2(v2, v3);
        }
    }
}

// ---------------------------------------------------------------------------
// Tensor-core flash attention (tf32 mma, causal), cp.async double-buffered K/V.
// Unchanged from R5 except: output written as fp16 (GEMM2 consumes it).
// ---------------------------------------------------------------------------
#define ABQ 128
#define ABK 64
#define KP  132
#define VP  136
#define PP  68
#define SKV (ABK * KP + ABK * VP)

#define ATTN_SMEM_FLOATS (2 * SKV + ABQ * PP)
#define ATTN_SMEM_BYTES  (ATTN_SMEM_FLOATS * 4)   // 172 KB

__global__ __launch_bounds__(256, 1)
void attn_tc(const float* __restrict__ qkv, __half* __restrict__ yh)
{
    extern __shared__ float sm[];
    float* Ps = sm + 2 * SKV;

    const int tid  = threadIdx.x;
    const int lane = tid & 31;
    const int warp = tid >> 5;
    const int g    = lane >> 2;
    const int tig  = lane & 3;
    const int qt   = (int)gridDim.x - 1 - (int)blockIdx.x;
    const int h    = blockIdx.y;
    const int b    = blockIdx.z;

    const size_t base  = (size_t)b * SEQ * QKVDIM + (size_t)h * HD;
    const float  scale = 0.08838834764831845f;
    const int    r0    = warp * 16;

    uint32_t qf[16][4];
    {
        float* QST = sm;
        for (int i = tid; i < ABQ * 32; i += 256) {
            int r = i >> 5, c4 = (i & 31) * 4;
            float4 v = *(const float4*)(qkv + base + (size_t)(qt * ABQ + r) * QKVDIM + c4);
            *(float4*)(QST + r * KP + c4) = v;
        }
        __syncthreads();
        #pragma unroll
        for (int ks = 0; ks < 16; ++ks) {
            int c = ks * 8 + tig;
            qf[ks][0] = f2tf(QST[(r0 + g)     * KP + c]     * scale);
            qf[ks][1] = f2tf(QST[(r0 + g + 8) * KP + c]     * scale);
            qf[ks][2] = f2tf(QST[(r0 + g)     * KP + c + 4] * scale);
            qf[ks][3] = f2tf(QST[(r0 + g + 8) * KP + c + 4] * scale);
        }
        __syncthreads();
    }

    float of[16][4];
    #pragma unroll
    for (int nb = 0; nb < 16; ++nb)
        #pragma unroll
        for (int j = 0; j < 4; ++j) of[nb][j] = 0.0f;

    float m0 = -1e30f, m1 = -1e30f, l0 = 0.0f, l1 = 0.0f;
    const int rowg0  = qt * ABQ + r0 + g;
    const int rowg1  = rowg0 + 8;
    const int rowmax = qt * ABQ + r0 + 15;
    const int ktmax  = 2 * qt + 1;

    auto load_kv = [&](int kt, int buf) {
        float* Kd = sm + buf * SKV;
        float* Vd = Kd + ABK * KP;
        #pragma unroll
        for (int q = 0; q < 8; ++q) {
            int i = tid + q * 256;
            int r = i >> 5, c4 = (i & 31) * 4;
            size_t tok = (size_t)(kt * ABK + r) * QKVDIM;
            cp_async16(Kd + r * KP + c4, qkv + base + CDIM     + tok + c4);
            cp_async16(Vd + r * VP + c4, qkv + base + 2 * CDIM + tok + c4);
        }
        asm volatile("cp.async.commit_group;\n");
    };

    load_kv(0, 0);

    for (int kt = 0; kt <= ktmax; ++kt) {
        if (kt + 1 <= ktmax) {
            load_kv(kt + 1, (kt + 1) & 1);
            asm volatile("cp.async.wait_group 1;\n");
        } else {
            asm volatile("cp.async.wait_group 0;\n");
        }
        __syncthreads();

        const float* Ks = sm + (kt & 1) * SKV;
        const float* Vs = Ks + ABK * KP;

        const int colbase = kt * ABK;
        const bool skip = colbase > rowmax;

        if (!skip) {
            float sf[8][4];
            #pragma unroll
            for (int nb = 0; nb < 8; ++nb)
                #pragma unroll
                for (int j = 0; j < 4; ++j) sf[nb][j] = 0.0f;

            #pragma unroll
            for (int ks = 0; ks < 16; ++ks) {
                uint32_t bf[8][2];
                #pragma unroll
                for (int nb = 0; nb < 8; ++nb) {
                    const float* p = Ks + (nb * 8 + g) * KP + ks * 8 + tig;
                    bf[nb][0] = __float_as_uint(p[0]);
                    bf[nb][1] = __float_as_uint(p[4]);
                }
                #pragma unroll
                for (int nb = 0; nb < 8; ++nb)
                    mma_tf32(sf[nb], qf[ks], bf[nb]);
            }

            if (colbase + ABK - 1 > rowg0) {
                #pragma unroll
                for (int nb = 0; nb < 8; ++nb) {
                    int col = colbase + nb * 8 + 2 * tig;
                    if (col     > rowg0) sf[nb][0] = -1e30f;
                    if (col + 1 > rowg0) sf[nb][1] = -1e30f;
                    if (col     > rowg1) sf[nb][2] = -1e30f;
                    if (col + 1 > rowg1) sf[nb][3] = -1e30f;
                }
            }

            float mx0 = -1e30f, mx1 = -1e30f;
            #pragma unroll
            for (int nb = 0; nb < 8; ++nb) {
                mx0 = fmaxf(mx0, fmaxf(sf[nb][0], sf[nb][1]));
                mx1 = fmaxf(mx1, fmaxf(sf[nb][2], sf[nb][3]));
            }
            mx0 = fmaxf(mx0, __shfl_xor_sync(0xffffffffu, mx0, 1));
            mx0 = fmaxf(mx0, __shfl_xor_sync(0xffffffffu, mx0, 2));
            mx1 = fmaxf(mx1, __shfl_xor_sync(0xffffffffu, mx1, 1));
            mx1 = fmaxf(mx1, __shfl_xor_sync(0xffffffffu, mx1, 2));

            float nm0 = fmaxf(m0, mx0);
            float nm1 = fmaxf(m1, mx1);
            float cr0 = __expf(m0 - nm0);
            float cr1 = __expf(m1 - nm1);

            float rs0 = 0.0f, rs1 = 0.0f;
            #pragma unroll
            for (int nb = 0; nb < 8; ++nb) {
                float e0 = __expf(sf[nb][0] - nm0);
                float e1 = __expf(sf[nb][1] - nm0);
                float e2 = __expf(sf[nb][2] - nm1);
                float e3 = __expf(sf[nb][3] - nm1);
                rs0 += e0 + e1;
                rs1 += e2 + e3;
                *(float2*)(Ps + (r0 + g)     * PP + nb * 8 + 2 * tig) =
                    make_float2(f2tf_f(e0), f2tf_f(e1));
                *(float2*)(Ps + (r0 + g + 8) * PP + nb * 8 + 2 * tig) =
                    make_float2(f2tf_f(e2), f2tf_f(e3));
            }
            rs0 += __shfl_xor_sync(0xffffffffu, rs0, 1);
            rs0 += __shfl_xor_sync(0xffffffffu, rs0, 2);
            rs1 += __shfl_xor_sync(0xffffffffu, rs1, 1);
            rs1 += __shfl_xor_sync(0xffffffffu, rs1, 2);

            m0 = nm0; m1 = nm1;
            l0 = l0 * cr0 + rs0;
            l1 = l1 * cr1 + rs1;

            #pragma unroll
            for (int nb = 0; nb < 16; ++nb) {
                of[nb][0] *= cr0; of[nb][1] *= cr0;
                of[nb][2] *= cr1; of[nb][3] *= cr1;
            }
            __syncwarp();

            #pragma unroll
            for (int ks2 = 0; ks2 < 8; ++ks2) {
                uint32_t pa[4];
                pa[0] = __float_as_uint(Ps[(r0 + g)     * PP + ks2 * 8 + tig]);
                pa[1] = __float_as_uint(Ps[(r0 + g + 8) * PP + ks2 * 8 + tig]);
                pa[2] = __float_as_uint(Ps[(r0 + g)     * PP + ks2 * 8 + tig + 4]);
                pa[3] = __float_as_uint(Ps[(r0 + g + 8) * PP + ks2 * 8 + tig + 4]);
                #pragma unroll
                for (int nb = 0; nb < 16; ++nb) {
                    uint32_t vb[2];
                    vb[0] = __float_as_uint(Vs[(ks2 * 8 + tig)     * VP + nb * 8 + g]);
                    vb[1] = __float_as_uint(Vs[(ks2 * 8 + tig + 4) * VP + nb * 8 + g]);
                    mma_tf32(of[nb], pa, vb);
                }
            }
            __syncwarp();
        }
        __syncthreads();
    }

    float inv0 = 1.0f / l0;
    float inv1 = 1.0f / l1;
    size_t yrow0 = (size_t)b * SEQ + rowg0;
    size_t yrow1 = (size_t)b * SEQ + rowg1;
    #pragma unroll
    for (int nb = 0; nb < 16; ++nb) {
        int col = h * HD + nb * 8 + 2 * tig;
        *(__half2*)(yh + yrow0 * CDIM + col) =
            __floats2half2_rn(of[nb][0] * inv0, of[nb][1] * inv0);
        *(__half2*)(yh + yrow1 * CDIM + col) =
            __floats2half2_rn(of[nb][2] * inv1, of[nb][3] * inv1);
    }
}

// ---------------------------------------------------------------------------
// kernel_launch
// ---------------------------------------------------------------------------
extern "C" void kernel_launch(void* const* d_in, const int* in_sizes, int n_in,
                              void* d_out, int out_size)
{
    const float* x     = (const float*)d_in[0];
    const float* Wqkv  = (const float*)d_in[1];   // [2048, 6144]
    const float* Wproj = (const float*)d_in[2];   // [2048, 2048]
    float* out = (float*)d_out;

    float  *qkv;
    __half *yh, *xh, *wqkvT, *wprjT;
    cudaGetSymbolAddress((void**)&qkv,   g_qkv);
    cudaGetSymbolAddress((void**)&yh,    g_yh);
    cudaGetSymbolAddress((void**)&xh,    g_xh);
    cudaGetSymbolAddress((void**)&wqkvT, g_wqkvT);
    cudaGetSymbolAddress((void**)&wprjT, g_wprjT);

    cudaFuncSetAttribute(gemm_fp16<true>,
                         cudaFuncAttributeMaxDynamicSharedMemorySize, GEMM_SMEM_BYTES);
    cudaFuncSetAttribute(gemm_fp16<false>,
                         cudaFuncAttributeMaxDynamicSharedMemorySize, GEMM_SMEM_BYTES);
    cudaFuncSetAttribute(attn_tc,
                         cudaFuncAttributeMaxDynamicSharedMemorySize, ATTN_SMEM_BYTES);

    // 0) convert inputs: x -> half, weights -> half transposed [N][K]
    {
        int n4x = MROWS * CDIM / 4;
        to_half<<<(n4x + 255) / 256, 256>>>(x, xh, n4x);
        transpose_half<<<dim3(QKVDIM / 32, CDIM / 32), dim3(32, 8)>>>(Wqkv,  wqkvT, CDIM, QKVDIM);
        transpose_half<<<dim3(CDIM / 32,  CDIM / 32), dim3(32, 8)>>>(Wproj, wprjT, CDIM, CDIM);
    }

    // 1) qkv = x @ Wqkv  (fp16 mma; output fp32, tf32-rounded for attention)
    gemm_fp16<true><<<dim3(QKVDIM / BN, MROWS / BM), 256, GEMM_SMEM_BYTES>>>(
        xh, wqkvT, qkv, MROWS, QKVDIM, CDIM);

    // 2) attention -> yh (fp16)
    attn_tc<<<dim3(SEQ / ABQ, NHEAD, BATCH), 256, ATTN_SMEM_BYTES>>>(qkv, yh);

    // 3) out = yh @ Wproj (fp16 mma, full fp32 output)
    gemm_fp16<false><<<dim3(CDIM / BN, MROWS / BM), 256, GEMM_SMEM_BYTES>>>(
        yh, wprjT, out, MROWS, CDIM, CDIM);
}

// round 13
// speedup vs baseline: 2.7826x; 1.1959x over previous
#include <cuda_runtime.h>
#include <cuda_fp16.h>
#include <cstdint>

// ---------------------------------------------------------------------------
// Problem constants
// ---------------------------------------------------------------------------
#define BATCH   4
#define SEQ     2048
#define CDIM    2048
#define NHEAD   16
#define HD      128
#define QKVDIM  (3 * CDIM)    // 6144
#define MROWS   (BATCH * SEQ) // 8192

__device__ __half g_qkv[(size_t)MROWS * QKVDIM];     // qkv in fp16
__device__ __half g_yh [(size_t)MROWS * CDIM];       // attention out, fp16
__device__ __half g_xh [(size_t)MROWS * CDIM];       // x in fp16
__device__ __half g_wqkvT[(size_t)QKVDIM * CDIM];    // Wqkv^T fp16
__device__ __half g_wprjT[(size_t)CDIM * CDIM];      // Wproj^T fp16

// ---------------------------------------------------------------------------
// Helpers
// ---------------------------------------------------------------------------
__device__ __forceinline__ void cp_async16(void* smem_dst, const void* gmem_src) {
    uint32_t s = (uint32_t)__cvta_generic_to_shared(smem_dst);
    asm volatile("cp.async.cg.shared.global [%0], [%1], 16;\n" :: "r"(s), "l"(gmem_src));
}
__device__ __forceinline__ void mma_fp16(float* d, const uint32_t* a, const uint32_t* b) {
    asm volatile(
        "mma.sync.aligned.m16n8k16.row.col.f32.f16.f16.f32 "
        "{%0,%1,%2,%3}, {%4,%5,%6,%7}, {%8,%9}, {%0,%1,%2,%3};"
        : "+f"(d[0]), "+f"(d[1]), "+f"(d[2]), "+f"(d[3])
        : "r"(a[0]), "r"(a[1]), "r"(a[2]), "r"(a[3]), "r"(b[0]), "r"(b[1]));
}
__device__ __forceinline__ uint32_t scale_pack(const __half* p, float s) {
    float2 f = __half22float2(*(const __half2*)p);
    __half2 h = __floats2half2_rn(f.x * s, f.y * s);
    return *(uint32_t*)&h;
}

// ---------------------------------------------------------------------------
// Prepass kernels
// ---------------------------------------------------------------------------
__global__ void to_half(const float* __restrict__ src, __half* __restrict__ dst, int n4)
{
    int i = blockIdx.x * blockDim.x + threadIdx.x;
    if (i < n4) {
        float4 v = ((const float4*)src)[i];
        __half2* d2 = (__half2*)dst + i * 2;
        d2[0] = __floats2half2_rn(v.x, v.y);
        d2[1] = __floats2half2_rn(v.z, v.w);
    }
}

__global__ void transpose_half(const float* __restrict__ src, __half* __restrict__ dst,
                               int K, int N)
{
    __shared__ float t[32][33];
    int nb = blockIdx.x * 32, kb = blockIdx.y * 32;
    int tx = threadIdx.x, ty = threadIdx.y;
    #pragma unroll
    for (int i = 0; i < 4; ++i)
        t[ty + i * 8][tx] = src[(size_t)(kb + ty + i * 8) * N + nb + tx];
    __syncthreads();
    #pragma unroll
    for (int i = 0; i < 4; ++i)
        dst[(size_t)(nb + ty + i * 8) * K + kb + tx] = __float2half(t[tx][ty + i * 8]);
}

// ---------------------------------------------------------------------------
// FP16 GEMM (proven R9 schedule): C = A[M,K] @ BT[N,K]^T, fp32 accum.
// ---------------------------------------------------------------------------
#define BM 128
#define BN 128
#define BKH 64
#define BKP 72

#define SMEM_AB_HALFS (BM * BKP)
#define SMEM_STAGE_H  (2 * SMEM_AB_HALFS)
#define GEMM_SMEM_BYTES (2 * SMEM_STAGE_H * 2)      // 73,728 B

template<bool OUT_HALF>
__global__ __launch_bounds__(256, 2)
void gemm_fp16(const __half* __restrict__ A, const __half* __restrict__ BT,
               void* __restrict__ Cv, int M, int N, int K)
{
    extern __shared__ __half smh[];

    const int tid  = threadIdx.x;
    const int lane = tid & 31;
    const int warp = tid >> 5;
    const int g    = lane >> 2;
    const int tig  = lane & 3;
    const int Wm   = (warp >> 1) * 32;
    const int Wn   = (warp & 1) * 64;
    const int brow = blockIdx.y * BM;
    const int bcol = blockIdx.x * BN;

    float acc[2][8][4];
    #pragma unroll
    for (int mt = 0; mt < 2; ++mt)
        #pragma unroll
        for (int nt = 0; nt < 8; ++nt)
            #pragma unroll
            for (int j = 0; j < 4; ++j) acc[mt][nt][j] = 0.0f;

    auto load_tile = [&](int k0, int buf) {
        __half* a_s = smh + buf * SMEM_STAGE_H;
        __half* b_s = a_s + SMEM_AB_HALFS;
        #pragma unroll
        for (int q = 0; q < 4; ++q) {
            int idx = tid + q * 256;
            int r = idx >> 3;
            int j = idx & 7;
            cp_async16(a_s + r * BKP + j * 8, A + (size_t)(brow + r) * K + k0 + j * 8);
        }
        #pragma unroll
        for (int q = 0; q < 4; ++q) {
            int idx = tid + q * 256;
            int r = idx >> 3;
            int j = idx & 7;
            cp_async16(b_s + r * BKP + j * 8, BT + (size_t)(bcol + r) * K + k0 + j * 8);
        }
        asm volatile("cp.async.commit_group;\n");
    };

    const int nIter = K / BKH;
    load_tile(0, 0);

    for (int it = 0; it < nIter; ++it) {
        if (it + 1 < nIter) {
            load_tile((it + 1) * BKH, (it + 1) & 1);
            asm volatile("cp.async.wait_group 1;\n");
        } else {
            asm volatile("cp.async.wait_group 0;\n");
        }
        __syncthreads();

        const __half* a_s = smh + (it & 1) * SMEM_STAGE_H;
        const __half* b_s = a_s + SMEM_AB_HALFS;

        #pragma unroll
        for (int ks = 0; ks < 4; ++ks) {
            uint32_t af[2][4], bf[8][2];
            #pragma unroll
            for (int mt = 0; mt < 2; ++mt) {
                const __half* p = a_s + (size_t)(Wm + mt * 16 + g) * BKP + ks * 16 + 2 * tig;
                af[mt][0] = *(const uint32_t*)(p);
                af[mt][1] = *(const uint32_t*)(p + 8 * BKP);
                af[mt][2] = *(const uint32_t*)(p + 8);
                af[mt][3] = *(const uint32_t*)(p + 8 * BKP + 8);
            }
            #pragma unroll
            for (int nt = 0; nt < 8; ++nt) {
                const __half* p = b_s + (size_t)(Wn + nt * 8 + g) * BKP + ks * 16 + 2 * tig;
                bf[nt][0] = *(const uint32_t*)(p);
                bf[nt][1] = *(const uint32_t*)(p + 8);
            }
            #pragma unroll
            for (int mt = 0; mt < 2; ++mt)
                #pragma unroll
                for (int nt = 0; nt < 8; ++nt)
                    mma_fp16(acc[mt][nt], af[mt], bf[nt]);
        }
        __syncthreads();
    }

    #pragma unroll
    for (int mt = 0; mt < 2; ++mt) {
        int row = brow + Wm + mt * 16 + g;
        #pragma unroll
        for (int nt = 0; nt < 8; ++nt) {
            int col = bcol + Wn + nt * 8 + tig * 2;
            if (OUT_HALF) {
                __half* C = (__half*)Cv;
                *(__half2*)(C + (size_t)row * N + col) =
                    __floats2half2_rn(acc[mt][nt][0], acc[mt][nt][1]);
                *(__half2*)(C + (size_t)(row + 8) * N + col) =
                    __floats2half2_rn(acc[mt][nt][2], acc[mt][nt][3]);
            } else {
                float* C = (float*)Cv;
                *(float2*)(C + (size_t)row * N + col) =
                    make_float2(acc[mt][nt][0], acc[mt][nt][1]);
                *(float2*)(C + (size_t)(row + 8) * N + col) =
                    make_float2(acc[mt][nt][2], acc[mt][nt][3]);
            }
        }
    }
}

// ---------------------------------------------------------------------------
// FP16 flash attention (causal). QK^T: GEMM-pattern B-frags from K tile.
// PV: GEMM-pattern B-frags from smem-transposed V (Vt[d][key]).
// FIX vs R11/R12: K/V tile pitch 136 halfs (rows are HD=128 halfs; the old
// pitch 72 overflowed every row into the next).
// ---------------------------------------------------------------------------
#define ABQ 128
#define ABK 64
#define KPH 136    // K tile pitch (halfs) >= HD, bank-safe (68 u32: 4g+tig)
#define VPH 136    // V tile pitch
#define VTP 72     // Vt pitch (rows are 64 keys wide)
#define PPH 72     // P tile pitch (rows are 64 keys wide)
#define QPH 136    // Q staging pitch

#define STAGE_H   (ABK * KPH + ABK * VPH)            // 17408 halfs
#define STAGE_B   (STAGE_H * 2)                      // 34816 B
#define PS_OFF    (2 * STAGE_B)                      // 69632
#define VT_OFF    (PS_OFF + ABQ * PPH * 2)           // 88064
#define ATTN_SMEM_BYTES (VT_OFF + HD * VTP * 2)      // 106,496 B

__global__ __launch_bounds__(256, 1)
void attn_fp16(const __half* __restrict__ qkv, __half* __restrict__ yh)
{
    extern __shared__ char smc[];
    __half* Ps = (__half*)(smc + PS_OFF);
    __half* Vt = (__half*)(smc + VT_OFF);   // [HD][VTP]

    const int tid  = threadIdx.x;
    const int lane = tid & 31;
    const int warp = tid >> 5;
    const int g    = lane >> 2;
    const int tig  = lane & 3;
    const int qt   = (int)gridDim.x - 1 - (int)blockIdx.x;
    const int h    = blockIdx.y;
    const int b    = blockIdx.z;

    const size_t base  = (size_t)b * SEQ * QKVDIM + (size_t)h * HD;
    const float  scale = 0.08838834764831845f;
    const int    r0    = warp * 16;

    // ---- Stage Q tile (fp16) in stage-0 region, build pre-scaled A-frags
    uint32_t qf[8][4];
    {
        __half* Qst = (__half*)smc;   // [ABQ][QPH] = 34816 B = STAGE_B (fits in 2 stages)
        #pragma unroll
        for (int q = 0; q < 8; ++q) {
            int i = tid + q * 256;
            int r = i >> 4, j = i & 15;
            *(uint4*)(Qst + (size_t)r * QPH + j * 8) =
                *(const uint4*)(qkv + base + (size_t)(qt * ABQ + r) * QKVDIM + j * 8);
        }
        __syncthreads();
        #pragma unroll
        for (int ks = 0; ks < 8; ++ks) {
            const __half* p = Qst + (size_t)(r0 + g) * QPH + ks * 16 + 2 * tig;
            qf[ks][0] = scale_pack(p, scale);
            qf[ks][1] = scale_pack(p + 8 * QPH, scale);
            qf[ks][2] = scale_pack(p + 8, scale);
            qf[ks][3] = scale_pack(p + 8 * QPH + 8, scale);
        }
        __syncthreads();
    }

    float of[16][4];
    #pragma unroll
    for (int nb = 0; nb < 16; ++nb)
        #pragma unroll
        for (int j = 0; j < 4; ++j) of[nb][j] = 0.0f;

    float m0 = -1e30f, m1 = -1e30f, l0 = 0.0f, l1 = 0.0f;
    const int rowg0  = qt * ABQ + r0 + g;
    const int rowg1  = rowg0 + 8;
    const int rowmax = qt * ABQ + r0 + 15;
    const int ktmax  = 2 * qt + 1;

    auto load_kv = [&](int kt, int buf) {
        __half* Kd = (__half*)(smc + buf * STAGE_B);
        __half* Vd = Kd + ABK * KPH;
        #pragma unroll
        for (int q = 0; q < 4; ++q) {
            int i = tid + q * 256;          // 0..1023
            int r = i >> 4, j = i & 15;     // r: 0..63 key, j: 16B chunk 0..15
            size_t tok = (size_t)(kt * ABK + r) * QKVDIM;
            cp_async16(Kd + (size_t)r * KPH + j * 8, qkv + base + CDIM     + tok + j * 8);
            cp_async16(Vd + (size_t)r * VPH + j * 8, qkv + base + 2 * CDIM + tok + j * 8);
        }
        asm volatile("cp.async.commit_group;\n");
    };

    load_kv(0, 0);

    for (int kt = 0; kt <= ktmax; ++kt) {
        if (kt + 1 <= ktmax) {
            load_kv(kt + 1, (kt + 1) & 1);
            asm volatile("cp.async.wait_group 1;\n");
        } else {
            asm volatile("cp.async.wait_group 0;\n");
        }
        __syncthreads();

        const __half* Ks = (const __half*)(smc + (kt & 1) * STAGE_B);
        const __half* Vs = Ks + ABK * KPH;

        // ---- cooperative transpose: V[64][VPH] -> Vt[128][VTP]
        #pragma unroll
        for (int q = 0; q < 8; ++q) {
            int i = tid + q * 256;                 // 0..2047
            int kpl = i & 3;
            int dpl = (i >> 2) & 7;
            int rest = i >> 5;
            int kp = kpl | ((rest & 7) << 2);      // 0..31 key pair
            int dp = dpl | ((rest >> 3) << 3);     // 0..63 d pair
            __half2 a = *(const __half2*)(Vs + (size_t)(2 * kp)     * VPH + 2 * dp);
            __half2 c = *(const __half2*)(Vs + (size_t)(2 * kp + 1) * VPH + 2 * dp);
            *(__half2*)(Vt + (size_t)(2 * dp)     * VTP + 2 * kp) = __lows2half2(a, c);
            *(__half2*)(Vt + (size_t)(2 * dp + 1) * VTP + 2 * kp) = __highs2half2(a, c);
        }
        __syncthreads();

        const int colbase = kt * ABK;
        const bool skip = colbase > rowmax;

        if (!skip) {
            // ---- S = Q K^T : 8 ksteps x 8 nb (m16n8k16)
            float sf[8][4];
            #pragma unroll
            for (int nb = 0; nb < 8; ++nb)
                #pragma unroll
                for (int j = 0; j < 4; ++j) sf[nb][j] = 0.0f;

            #pragma unroll
            for (int ks = 0; ks < 8; ++ks) {
                uint32_t bf[8][2];
                #pragma unroll
                for (int nb = 0; nb < 8; ++nb) {
                    const __half* p = Ks + (size_t)(nb * 8 + g) * KPH + ks * 16 + 2 * tig;
                    bf[nb][0] = *(const uint32_t*)(p);
                    bf[nb][1] = *(const uint32_t*)(p + 8);
                }
                #pragma unroll
                for (int nb = 0; nb < 8; ++nb)
                    mma_fp16(sf[nb], qf[ks], bf[nb]);
            }

            // ---- causal mask
            if (colbase + ABK - 1 > rowg0) {
                #pragma unroll
                for (int nb = 0; nb < 8; ++nb) {
                    int col = colbase + nb * 8 + 2 * tig;
                    if (col     > rowg0) sf[nb][0] = -1e30f;
                    if (col + 1 > rowg0) sf[nb][1] = -1e30f;
                    if (col     > rowg1) sf[nb][2] = -1e30f;
                    if (col + 1 > rowg1) sf[nb][3] = -1e30f;
                }
            }

            // ---- online softmax (fp32)
            float mx0 = -1e30f, mx1 = -1e30f;
            #pragma unroll
            for (int nb = 0; nb < 8; ++nb) {
                mx0 = fmaxf(mx0, fmaxf(sf[nb][0], sf[nb][1]));
                mx1 = fmaxf(mx1, fmaxf(sf[nb][2], sf[nb][3]));
            }
            mx0 = fmaxf(mx0, __shfl_xor_sync(0xffffffffu, mx0, 1));
            mx0 = fmaxf(mx0, __shfl_xor_sync(0xffffffffu, mx0, 2));
            mx1 = fmaxf(mx1, __shfl_xor_sync(0xffffffffu, mx1, 1));
            mx1 = fmaxf(mx1, __shfl_xor_sync(0xffffffffu, mx1, 2));

            float nm0 = fmaxf(m0, mx0);
            float nm1 = fmaxf(m1, mx1);
            float cr0 = __expf(m0 - nm0);
            float cr1 = __expf(m1 - nm1);

            float rs0 = 0.0f, rs1 = 0.0f;
            #pragma unroll
            for (int nb = 0; nb < 8; ++nb) {
                float e0 = __expf(sf[nb][0] - nm0);
                float e1 = __expf(sf[nb][1] - nm0);
                float e2 = __expf(sf[nb][2] - nm1);
                float e3 = __expf(sf[nb][3] - nm1);
                rs0 += e0 + e1;
                rs1 += e2 + e3;
                *(__half2*)(Ps + (size_t)(r0 + g)     * PPH + nb * 8 + 2 * tig) =
                    __floats2half2_rn(e0, e1);
                *(__half2*)(Ps + (size_t)(r0 + g + 8) * PPH + nb * 8 + 2 * tig) =
                    __floats2half2_rn(e2, e3);
            }
            rs0 += __shfl_xor_sync(0xffffffffu, rs0, 1);
            rs0 += __shfl_xor_sync(0xffffffffu, rs0, 2);
            rs1 += __shfl_xor_sync(0xffffffffu, rs1, 1);
            rs1 += __shfl_xor_sync(0xffffffffu, rs1, 2);

            m0 = nm0; m1 = nm1;
            l0 = l0 * cr0 + rs0;
            l1 = l1 * cr1 + rs1;

            #pragma unroll
            for (int nb = 0; nb < 16; ++nb) {
                of[nb][0] *= cr0; of[nb][1] *= cr0;
                of[nb][2] *= cr1; of[nb][3] *= cr1;
            }
            __syncwarp();

            // ---- O += P V : 4 ksteps x 16 nb, B-frags from Vt (GEMM pattern)
            #pragma unroll
            for (int ks2 = 0; ks2 < 4; ++ks2) {
                uint32_t pa[4];
                const __half* pp = Ps + (size_t)(r0 + g) * PPH + ks2 * 16 + 2 * tig;
                pa[0] = *(const uint32_t*)(pp);
                pa[1] = *(const uint32_t*)(pp + 8 * PPH);
                pa[2] = *(const uint32_t*)(pp + 8);
                pa[3] = *(const uint32_t*)(pp + 8 * PPH + 8);

                #pragma unroll
                for (int nb = 0; nb < 16; ++nb) {
                    const __half* p = Vt + (size_t)(nb * 8 + g) * VTP + ks2 * 16 + 2 * tig;
                    uint32_t vb[2] = { *(const uint32_t*)(p), *(const uint32_t*)(p + 8) };
                    mma_fp16(of[nb], pa, vb);
                }
            }
            __syncwarp();
        }
        __syncthreads();   // guards stage AND Vt overwrite next iter
    }

    // ---- normalize, write yh (fp16)
    float inv0 = 1.0f / l0;
    float inv1 = 1.0f / l1;
    size_t yrow0 = (size_t)b * SEQ + rowg0;
    size_t yrow1 = (size_t)b * SEQ + rowg1;
    #pragma unroll
    for (int nb = 0; nb < 16; ++nb) {
        int col = h * HD + nb * 8 + 2 * tig;
        *(__half2*)(yh + yrow0 * CDIM + col) =
            __floats2half2_rn(of[nb][0] * inv0, of[nb][1] * inv0);
        *(__half2*)(yh + yrow1 * CDIM + col) =
            __floats2half2_rn(of[nb][2] * inv1, of[nb][3] * inv1);
    }
}

// ---------------------------------------------------------------------------
// kernel_launch
// ---------------------------------------------------------------------------
extern "C" void kernel_launch(void* const* d_in, const int* in_sizes, int n_in,
                              void* d_out, int out_size)
{
    const float* x     = (const float*)d_in[0];
    const float* Wqkv  = (const float*)d_in[1];
    const float* Wproj = (const float*)d_in[2];
    float* out = (float*)d_out;

    __half *qkv, *yh, *xh, *wqkvT, *wprjT;
    cudaGetSymbolAddress((void**)&qkv,   g_qkv);
    cudaGetSymbolAddress((void**)&yh,    g_yh);
    cudaGetSymbolAddress((void**)&xh,    g_xh);
    cudaGetSymbolAddress((void**)&wqkvT, g_wqkvT);
    cudaGetSymbolAddress((void**)&wprjT, g_wprjT);

    cudaFuncSetAttribute(gemm_fp16<true>,
                         cudaFuncAttributeMaxDynamicSharedMemorySize, GEMM_SMEM_BYTES);
    cudaFuncSetAttribute(gemm_fp16<false>,
                         cudaFuncAttributeMaxDynamicSharedMemorySize, GEMM_SMEM_BYTES);
    cudaFuncSetAttribute(attn_fp16,
                         cudaFuncAttributeMaxDynamicSharedMemorySize, ATTN_SMEM_BYTES);

    // 0) inputs -> fp16 (weights transposed to [N][K])
    {
        int n4x = MROWS * CDIM / 4;
        to_half<<<(n4x + 255) / 256, 256>>>(x, xh, n4x);
        transpose_half<<<dim3(QKVDIM / 32, CDIM / 32), dim3(32, 8)>>>(Wqkv,  wqkvT, CDIM, QKVDIM);
        transpose_half<<<dim3(CDIM / 32,  CDIM / 32), dim3(32, 8)>>>(Wproj, wprjT, CDIM, CDIM);
    }

    // 1) qkv = x @ Wqkv  (fp16 out)
    gemm_fp16<true><<<dim3(QKVDIM / BN, MROWS / BM), 256, GEMM_SMEM_BYTES>>>(
        xh, wqkvT, qkv, MROWS, QKVDIM, CDIM);

    // 2) attention (fp16 mma) -> yh
    attn_fp16<<<dim3(SEQ / ABQ, NHEAD, BATCH), 256, ATTN_SMEM_BYTES>>>(qkv, yh);

    // 3) out = yh @ Wproj (fp32 out)
    gemm_fp16<false><<<dim3(CDIM / BN, MROWS / BM), 256, GEMM_SMEM_BYTES>>>(
        yh, wprjT, out, MROWS, CDIM, CDIM);
}

// round 15
// speedup vs baseline: 3.0356x; 1.0909x over previous
#include <cuda_runtime.h>
#include <cuda_fp16.h>
#include <cstdint>

// ---------------------------------------------------------------------------
// Problem constants
// ---------------------------------------------------------------------------
#define BATCH   4
#define SEQ     2048
#define CDIM    2048
#define NHEAD   16
#define HD      128
#define QKVDIM  (3 * CDIM)    // 6144
#define MROWS   (BATCH * SEQ) // 8192

__device__ __half g_qkv[(size_t)MROWS * QKVDIM];     // qkv in fp16
__device__ __half g_yh [(size_t)MROWS * CDIM];       // attention out, fp16
__device__ __half g_xh [(size_t)MROWS * CDIM];       // x in fp16
__device__ __half g_wqkvT[(size_t)QKVDIM * CDIM];    // Wqkv^T fp16
__device__ __half g_wprjT[(size_t)CDIM * CDIM];      // Wproj^T fp16

// ---------------------------------------------------------------------------
// Helpers
// ---------------------------------------------------------------------------
__device__ __forceinline__ void cp_async16(void* smem_dst, const void* gmem_src) {
    uint32_t s = (uint32_t)__cvta_generic_to_shared(smem_dst);
    asm volatile("cp.async.cg.shared.global [%0], [%1], 16;\n" :: "r"(s), "l"(gmem_src));
}
__device__ __forceinline__ void mma_fp16(float* d, const uint32_t* a, const uint32_t* b) {
    asm volatile(
        "mma.sync.aligned.m16n8k16.row.col.f32.f16.f16.f32 "
        "{%0,%1,%2,%3}, {%4,%5,%6,%7}, {%8,%9}, {%0,%1,%2,%3};"
        : "+f"(d[0]), "+f"(d[1]), "+f"(d[2]), "+f"(d[3])
        : "r"(a[0]), "r"(a[1]), "r"(a[2]), "r"(a[3]), "r"(b[0]), "r"(b[1]));
}
// non-transposed ldmatrix x4: lane l receives row l/4, cols 2(l%4)..+1 of each matrix
__device__ __forceinline__ void ldmx4(uint32_t& r0, uint32_t& r1,
                                      uint32_t& r2, uint32_t& r3, uint32_t addr) {
    asm volatile("ldmatrix.sync.aligned.m8n8.x4.shared.b16 {%0,%1,%2,%3}, [%4];"
                 : "=r"(r0), "=r"(r1), "=r"(r2), "=r"(r3) : "r"(addr));
}
__device__ __forceinline__ uint32_t scale_pack(const __half* p, float s) {
    float2 f = __half22float2(*(const __half2*)p);
    __half2 h = __floats2half2_rn(f.x * s, f.y * s);
    return *(uint32_t*)&h;
}

// ---------------------------------------------------------------------------
// Prepass kernels
// ---------------------------------------------------------------------------
__global__ void to_half(const float* __restrict__ src, __half* __restrict__ dst, int n4)
{
    int i = blockIdx.x * blockDim.x + threadIdx.x;
    if (i < n4) {
        float4 v = ((const float4*)src)[i];
        __half2* d2 = (__half2*)dst + i * 2;
        d2[0] = __floats2half2_rn(v.x, v.y);
        d2[1] = __floats2half2_rn(v.z, v.w);
    }
}

__global__ void transpose_half(const float* __restrict__ src, __half* __restrict__ dst,
                               int K, int N)
{
    __shared__ float t[32][33];
    int nb = blockIdx.x * 32, kb = blockIdx.y * 32;
    int tx = threadIdx.x, ty = threadIdx.y;
    #pragma unroll
    for (int i = 0; i < 4; ++i)
        t[ty + i * 8][tx] = src[(size_t)(kb + ty + i * 8) * N + nb + tx];
    __syncthreads();
    #pragma unroll
    for (int i = 0; i < 4; ++i)
        dst[(size_t)(nb + ty + i * 8) * K + kb + tx] = __float2half(t[tx][ty + i * 8]);
}

// ---------------------------------------------------------------------------
// FP16 GEMM: C = A[M,K] @ BT[N,K]^T, fp32 accum.
// R14: fragment loads via ldmatrix.x4 (6 instr/ks instead of 24 LDS.32).
// ---------------------------------------------------------------------------
#define BM 128
#define BN 128
#define BKH 64
#define BKP 72

#define SMEM_AB_HALFS (BM * BKP)
#define SMEM_STAGE_H  (2 * SMEM_AB_HALFS)
#define GEMM_SMEM_BYTES (2 * SMEM_STAGE_H * 2)      // 73,728 B

template<bool OUT_HALF>
__global__ __launch_bounds__(256, 2)
void gemm_fp16(const __half* __restrict__ A, const __half* __restrict__ BT,
               void* __restrict__ Cv, int M, int N, int K)
{
    extern __shared__ __half smh[];

    const int tid  = threadIdx.x;
    const int lane = tid & 31;
    const int warp = tid >> 5;
    const int g    = lane >> 2;
    const int tig  = lane & 3;
    const int Wm   = (warp >> 1) * 32;
    const int Wn   = (warp & 1) * 64;
    const int brow = blockIdx.y * BM;
    const int bcol = blockIdx.x * BN;

    // ldmatrix per-lane source rows/cols (see derivation in commit msg):
    // A: matrices {rows, rows+8, cols+8x} -> af[0..3]
    const int arow = ((lane >> 3) & 1) * 8 + (lane & 7);
    const int acol = ((lane >> 4) & 1) * 8;
    // B: matrices {nt rows k0, nt rows k8, nt+1 rows k0, nt+1 rows k8}
    const int brw  = ((lane >> 4) & 1) * 8 + (lane & 7);
    const int bcl  = ((lane >> 3) & 1) * 8;

    const uint32_t smem_base_u32 = (uint32_t)__cvta_generic_to_shared(smh);
    const uint32_t aoff = ((Wm + arow) * BKP + acol) * 2;
    const uint32_t boff = (SMEM_AB_HALFS + (Wn + brw) * BKP + bcl) * 2;

    float acc[2][8][4];
    #pragma unroll
    for (int mt = 0; mt < 2; ++mt)
        #pragma unroll
        for (int nt = 0; nt < 8; ++nt)
            #pragma unroll
            for (int j = 0; j < 4; ++j) acc[mt][nt][j] = 0.0f;

    auto load_tile = [&](int k0, int buf) {
        __half* a_s = smh + buf * SMEM_STAGE_H;
        __half* b_s = a_s + SMEM_AB_HALFS;
        #pragma unroll
        for (int q = 0; q < 4; ++q) {
            int idx = tid + q * 256;
            int r = idx >> 3;
            int j = idx & 7;
            cp_async16(a_s + r * BKP + j * 8, A + (size_t)(brow + r) * K + k0 + j * 8);
        }
        #pragma unroll
        for (int q = 0; q < 4; ++q) {
            int idx = tid + q * 256;
            int r = idx >> 3;
            int j = idx & 7;
            cp_async16(b_s + r * BKP + j * 8, BT + (size_t)(bcol + r) * K + k0 + j * 8);
        }
        asm volatile("cp.async.commit_group;\n");
    };

    const int nIter = K / BKH;
    load_tile(0, 0);

    for (int it = 0; it < nIter; ++it) {
        if (it + 1 < nIter) {
            load_tile((it + 1) * BKH, (it + 1) & 1);
            asm volatile("cp.async.wait_group 1;\n");
        } else {
            asm volatile("cp.async.wait_group 0;\n");
        }
        __syncthreads();

        const uint32_t stage = smem_base_u32 + (uint32_t)((it & 1) * SMEM_STAGE_H * 2);
        const uint32_t abase = stage + aoff;
        const uint32_t bbase = stage + boff;

        #pragma unroll
        for (int ks = 0; ks < 4; ++ks) {
            uint32_t af[2][4];
            #pragma unroll
            for (int mt = 0; mt < 2; ++mt)
                ldmx4(af[mt][0], af[mt][1], af[mt][2], af[mt][3],
                      abase + (uint32_t)(mt * 16 * BKP * 2 + ks * 32));
            #pragma unroll
            for (int nt2 = 0; nt2 < 4; ++nt2) {
                uint32_t b0, b1, b2, b3;
                ldmx4(b0, b1, b2, b3,
                      bbase + (uint32_t)(nt2 * 16 * BKP * 2 + ks * 32));
                uint32_t vb0[2] = {b0, b1};
                uint32_t vb1[2] = {b2, b3};
                #pragma unroll
                for (int mt = 0; mt < 2; ++mt) {
                    mma_fp16(acc[mt][2 * nt2],     af[mt], vb0);
                    mma_fp16(acc[mt][2 * nt2 + 1], af[mt], vb1);
                }
            }
        }
        __syncthreads();
    }

    #pragma unroll
    for (int mt = 0; mt < 2; ++mt) {
        int row = brow + Wm + mt * 16 + g;
        #pragma unroll
        for (int nt = 0; nt < 8; ++nt) {
            int col = bcol + Wn + nt * 8 + tig * 2;
            if (OUT_HALF) {
                __half* C = (__half*)Cv;
                *(__half2*)(C + (size_t)row * N + col) =
                    __floats2half2_rn(acc[mt][nt][0], acc[mt][nt][1]);
                *(__half2*)(C + (size_t)(row + 8) * N + col) =
                    __floats2half2_rn(acc[mt][nt][2], acc[mt][nt][3]);
            } else {
                float* C = (float*)Cv;
                *(float2*)(C + (size_t)row * N + col) =
                    make_float2(acc[mt][nt][0], acc[mt][nt][1]);
                *(float2*)(C + (size_t)(row + 8) * N + col) =
                    make_float2(acc[mt][nt][2], acc[mt][nt][3]);
            }
        }
    }
}

// ---------------------------------------------------------------------------
// FP16 flash attention (causal) — unchanged from R13 (proven).
// ---------------------------------------------------------------------------
#define ABQ 128
#define ABK 64
#define KPH 136
#define VPH 136
#define VTP 72
#define PPH 72
#define QPH 136

#define STAGE_H   (ABK * KPH + ABK * VPH)            // 17408 halfs
#define STAGE_B   (STAGE_H * 2)                      // 34816 B
#define PS_OFF    (2 * STAGE_B)                      // 69632
#define VT_OFF    (PS_OFF + ABQ * PPH * 2)           // 88064
#define ATTN_SMEM_BYTES (VT_OFF + HD * VTP * 2)      // 106,496 B

__global__ __launch_bounds__(256, 1)
void attn_fp16(const __half* __restrict__ qkv, __half* __restrict__ yh)
{
    extern __shared__ char smc[];
    __half* Ps = (__half*)(smc + PS_OFF);
    __half* Vt = (__half*)(smc + VT_OFF);

    const int tid  = threadIdx.x;
    const int lane = tid & 31;
    const int warp = tid >> 5;
    const int g    = lane >> 2;
    const int tig  = lane & 3;
    const int qt   = (int)gridDim.x - 1 - (int)blockIdx.x;
    const int h    = blockIdx.y;
    const int b    = blockIdx.z;

    const size_t base  = (size_t)b * SEQ * QKVDIM + (size_t)h * HD;
    const float  scale = 0.08838834764831845f;
    const int    r0    = warp * 16;

    uint32_t qf[8][4];
    {
        __half* Qst = (__half*)smc;
        #pragma unroll
        for (int q = 0; q < 8; ++q) {
            int i = tid + q * 256;
            int r = i >> 4, j = i & 15;
            *(uint4*)(Qst + (size_t)r * QPH + j * 8) =
                *(const uint4*)(qkv + base + (size_t)(qt * ABQ + r) * QKVDIM + j * 8);
        }
        __syncthreads();
        #pragma unroll
        for (int ks = 0; ks < 8; ++ks) {
            const __half* p = Qst + (size_t)(r0 + g) * QPH + ks * 16 + 2 * tig;
            qf[ks][0] = scale_pack(p, scale);
            qf[ks][1] = scale_pack(p + 8 * QPH, scale);
            qf[ks][2] = scale_pack(p + 8, scale);
            qf[ks][3] = scale_pack(p + 8 * QPH + 8, scale);
        }
        __syncthreads();
    }

    float of[16][4];
    #pragma unroll
    for (int nb = 0; nb < 16; ++nb)
        #pragma unroll
        for (int j = 0; j < 4; ++j) of[nb][j] = 0.0f;

    float m0 = -1e30f, m1 = -1e30f, l0 = 0.0f, l1 = 0.0f;
    const int rowg0  = qt * ABQ + r0 + g;
    const int rowg1  = rowg0 + 8;
    const int rowmax = qt * ABQ + r0 + 15;
    const int ktmax  = 2 * qt + 1;

    auto load_kv = [&](int kt, int buf) {
        __half* Kd = (__half*)(smc + buf * STAGE_B);
        __half* Vd = Kd + ABK * KPH;
        #pragma unroll
        for (int q = 0; q < 4; ++q) {
            int i = tid + q * 256;
            int r = i >> 4, j = i & 15;
            size_t tok = (size_t)(kt * ABK + r) * QKVDIM;
            cp_async16(Kd + (size_t)r * KPH + j * 8, qkv + base + CDIM     + tok + j * 8);
            cp_async16(Vd + (size_t)r * VPH + j * 8, qkv + base + 2 * CDIM + tok + j * 8);
        }
        asm volatile("cp.async.commit_group;\n");
    };

    load_kv(0, 0);

    for (int kt = 0; kt <= ktmax; ++kt) {
        if (kt + 1 <= ktmax) {
            load_kv(kt + 1, (kt + 1) & 1);
            asm volatile("cp.async.wait_group 1;\n");
        } else {
            asm volatile("cp.async.wait_group 0;\n");
        }
        __syncthreads();

        const __half* Ks = (const __half*)(smc + (kt & 1) * STAGE_B);
        const __half* Vs = Ks + ABK * KPH;

        #pragma unroll
        for (int q = 0; q < 8; ++q) {
            int i = tid + q * 256;
            int kpl = i & 3;
            int dpl = (i >> 2) & 7;
            int rest = i >> 5;
            int kp = kpl | ((rest & 7) << 2);
            int dp = dpl | ((rest >> 3) << 3);
            __half2 a = *(const __half2*)(Vs + (size_t)(2 * kp)     * VPH + 2 * dp);
            __half2 c = *(const __half2*)(Vs + (size_t)(2 * kp + 1) * VPH + 2 * dp);
            *(__half2*)(Vt + (size_t)(2 * dp)     * VTP + 2 * kp) = __lows2half2(a, c);
            *(__half2*)(Vt + (size_t)(2 * dp + 1) * VTP + 2 * kp) = __highs2half2(a, c);
        }
        __syncthreads();

        const int colbase = kt * ABK;
        const bool skip = colbase > rowmax;

        if (!skip) {
            float sf[8][4];
            #pragma unroll
            for (int nb = 0; nb < 8; ++nb)
                #pragma unroll
                for (int j = 0; j < 4; ++j) sf[nb][j] = 0.0f;

            #pragma unroll
            for (int ks = 0; ks < 8; ++ks) {
                uint32_t bf[8][2];
                #pragma unroll
                for (int nb = 0; nb < 8; ++nb) {
                    const __half* p = Ks + (size_t)(nb * 8 + g) * KPH + ks * 16 + 2 * tig;
                    bf[nb][0] = *(const uint32_t*)(p);
                    bf[nb][1] = *(const uint32_t*)(p + 8);
                }
                #pragma unroll
                for (int nb = 0; nb < 8; ++nb)
                    mma_fp16(sf[nb], qf[ks], bf[nb]);
            }

            if (colbase + ABK - 1 > rowg0) {
                #pragma unroll
                for (int nb = 0; nb < 8; ++nb) {
                    int col = colbase + nb * 8 + 2 * tig;
                    if (col     > rowg0) sf[nb][0] = -1e30f;
                    if (col + 1 > rowg0) sf[nb][1] = -1e30f;
                    if (col     > rowg1) sf[nb][2] = -1e30f;
                    if (col + 1 > rowg1) sf[nb][3] = -1e30f;
                }
            }

            float mx0 = -1e30f, mx1 = -1e30f;
            #pragma unroll
            for (int nb = 0; nb < 8; ++nb) {
                mx0 = fmaxf(mx0, fmaxf(sf[nb][0], sf[nb][1]));
                mx1 = fmaxf(mx1, fmaxf(sf[nb][2], sf[nb][3]));
            }
            mx0 = fmaxf(mx0, __shfl_xor_sync(0xffffffffu, mx0, 1));
            mx0 = fmaxf(mx0, __shfl_xor_sync(0xffffffffu, mx0, 2));
            mx1 = fmaxf(mx1, __shfl_xor_sync(0xffffffffu, mx1, 1));
            mx1 = fmaxf(mx1, __shfl_xor_sync(0xffffffffu, mx1, 2));

            float nm0 = fmaxf(m0, mx0);
            float nm1 = fmaxf(m1, mx1);
            float cr0 = __expf(m0 - nm0);
            float cr1 = __expf(m1 - nm1);

            float rs0 = 0.0f, rs1 = 0.0f;
            #pragma unroll
            for (int nb = 0; nb < 8; ++nb) {
                float e0 = __expf(sf[nb][0] - nm0);
                float e1 = __expf(sf[nb][1] - nm0);
                float e2 = __expf(sf[nb][2] - nm1);
                float e3 = __expf(sf[nb][3] - nm1);
                rs0 += e0 + e1;
                rs1 += e2 + e3;
                *(__half2*)(Ps + (size_t)(r0 + g)     * PPH + nb * 8 + 2 * tig) =
                    __floats2half2_rn(e0, e1);
                *(__half2*)(Ps + (size_t)(r0 + g + 8) * PPH + nb * 8 + 2 * tig) =
                    __floats2half2_rn(e2, e3);
            }
            rs0 += __shfl_xor_sync(0xffffffffu, rs0, 1);
            rs0 += __shfl_xor_sync(0xffffffffu, rs0, 2);
            rs1 += __shfl_xor_sync(0xffffffffu, rs1, 1);
            rs1 += __shfl_xor_sync(0xffffffffu, rs1, 2);

            m0 = nm0; m1 = nm1;
            l0 = l0 * cr0 + rs0;
            l1 = l1 * cr1 + rs1;

            #pragma unroll
            for (int nb = 0; nb < 16; ++nb) {
                of[nb][0] *= cr0; of[nb][1] *= cr0;
                of[nb][2] *= cr1; of[nb][3] *= cr1;
            }
            __syncwarp();

            #pragma unroll
            for (int ks2 = 0; ks2 < 4; ++ks2) {
                uint32_t pa[4];
                const __half* pp = Ps + (size_t)(r0 + g) * PPH + ks2 * 16 + 2 * tig;
                pa[0] = *(const uint32_t*)(pp);
                pa[1] = *(const uint32_t*)(pp + 8 * PPH);
                pa[2] = *(const uint32_t*)(pp + 8);
                pa[3] = *(const uint32_t*)(pp + 8 * PPH + 8);

                #pragma unroll
                for (int nb = 0; nb < 16; ++nb) {
                    const __half* p = Vt + (size_t)(nb * 8 + g) * VTP + ks2 * 16 + 2 * tig;
                    uint32_t vb[2] = { *(const uint32_t*)(p), *(const uint32_t*)(p + 8) };
                    mma_fp16(of[nb], pa, vb);
                }
            }
            __syncwarp();
        }
        __syncthreads();
    }

    float inv0 = 1.0f / l0;
    float inv1 = 1.0f / l1;
    size_t yrow0 = (size_t)b * SEQ + rowg0;
    size_t yrow1 = (size_t)b * SEQ + rowg1;
    #pragma unroll
    for (int nb = 0; nb < 16; ++nb) {
        int col = h * HD + nb * 8 + 2 * tig;
        *(__half2*)(yh + yrow0 * CDIM + col) =
            __floats2half2_rn(of[nb][0] * inv0, of[nb][1] * inv0);
        *(__half2*)(yh + yrow1 * CDIM + col) =
            __floats2half2_rn(of[nb][2] * inv1, of[nb][3] * inv1);
    }
}

// ---------------------------------------------------------------------------
// kernel_launch
// ---------------------------------------------------------------------------
extern "C" void kernel_launch(void* const* d_in, const int* in_sizes, int n_in,
                              void* d_out, int out_size)
{
    const float* x     = (const float*)d_in[0];
    const float* Wqkv  = (const float*)d_in[1];
    const float* Wproj = (const float*)d_in[2];
    float* out = (float*)d_out;

    __half *qkv, *yh, *xh, *wqkvT, *wprjT;
    cudaGetSymbolAddress((void**)&qkv,   g_qkv);
    cudaGetSymbolAddress((void**)&yh,    g_yh);
    cudaGetSymbolAddress((void**)&xh,    g_xh);
    cudaGetSymbolAddress((void**)&wqkvT, g_wqkvT);
    cudaGetSymbolAddress((void**)&wprjT, g_wprjT);

    cudaFuncSetAttribute(gemm_fp16<true>,
                         cudaFuncAttributeMaxDynamicSharedMemorySize, GEMM_SMEM_BYTES);
    cudaFuncSetAttribute(gemm_fp16<false>,
                         cudaFuncAttributeMaxDynamicSharedMemorySize, GEMM_SMEM_BYTES);
    cudaFuncSetAttribute(attn_fp16,
                         cudaFuncAttributeMaxDynamicSharedMemorySize, ATTN_SMEM_BYTES);

    // 0) inputs -> fp16 (weights transposed to [N][K])
    {
        int n4x = MROWS * CDIM / 4;
        to_half<<<(n4x + 255) / 256, 256>>>(x, xh, n4x);
        transpose_half<<<dim3(QKVDIM / 32, CDIM / 32), dim3(32, 8)>>>(Wqkv,  wqkvT, CDIM, QKVDIM);
        transpose_half<<<dim3(CDIM / 32,  CDIM / 32), dim3(32, 8)>>>(Wproj, wprjT, CDIM, CDIM);
    }

    // 1) qkv = x @ Wqkv  (fp16 out)
    gemm_fp16<true><<<dim3(QKVDIM / BN, MROWS / BM), 256, GEMM_SMEM_BYTES>>>(
        xh, wqkvT, qkv, MROWS, QKVDIM, CDIM);

    // 2) attention (fp16 mma) -> yh
    attn_fp16<<<dim3(SEQ / ABQ, NHEAD, BATCH), 256, ATTN_SMEM_BYTES>>>(qkv, yh);

    // 3) out = yh @ Wproj (fp32 out)
    gemm_fp16<false><<<dim3(CDIM / BN, MROWS / BM), 256, GEMM_SMEM_BYTES>>>(
        yh, wprjT, out, MROWS, CDIM, CDIM);
}

// round 17
// speedup vs baseline: 3.1710x; 1.0446x over previous
#include <cuda_runtime.h>
#include <cuda_fp16.h>
#include <cstdint>

// ---------------------------------------------------------------------------
// Problem constants
// ---------------------------------------------------------------------------
#define BATCH   4
#define SEQ     2048
#define CDIM    2048
#define NHEAD   16
#define HD      128
#define QKVDIM  (3 * CDIM)    // 6144
#define MROWS   (BATCH * SEQ) // 8192

__device__ __half g_qkv[(size_t)MROWS * QKVDIM];     // qkv in fp16
__device__ __half g_yh [(size_t)MROWS * CDIM];       // attention out, fp16
__device__ __half g_xh [(size_t)MROWS * CDIM];       // x in fp16
__device__ __half g_wqkvT[(size_t)QKVDIM * CDIM];    // Wqkv^T fp16
__device__ __half g_wprjT[(size_t)CDIM * CDIM];      // Wproj^T fp16

// ---------------------------------------------------------------------------
// Helpers
// ---------------------------------------------------------------------------
__device__ __forceinline__ void cp_async16(void* smem_dst, const void* gmem_src) {
    uint32_t s = (uint32_t)__cvta_generic_to_shared(smem_dst);
    asm volatile("cp.async.cg.shared.global [%0], [%1], 16;\n" :: "r"(s), "l"(gmem_src));
}
__device__ __forceinline__ void mma_fp16(float* d, const uint32_t* a, const uint32_t* b) {
    asm volatile(
        "mma.sync.aligned.m16n8k16.row.col.f32.f16.f16.f32 "
        "{%0,%1,%2,%3}, {%4,%5,%6,%7}, {%8,%9}, {%0,%1,%2,%3};"
        : "+f"(d[0]), "+f"(d[1]), "+f"(d[2]), "+f"(d[3])
        : "r"(a[0]), "r"(a[1]), "r"(a[2]), "r"(a[3]), "r"(b[0]), "r"(b[1]));
}
__device__ __forceinline__ void ldmx4(uint32_t& r0, uint32_t& r1,
                                      uint32_t& r2, uint32_t& r3, uint32_t addr) {
    asm volatile("ldmatrix.sync.aligned.m8n8.x4.shared.b16 {%0,%1,%2,%3}, [%4];"
                 : "=r"(r0), "=r"(r1), "=r"(r2), "=r"(r3) : "r"(addr));
}
__device__ __forceinline__ void ldmx4t(uint32_t& r0, uint32_t& r1,
                                       uint32_t& r2, uint32_t& r3, uint32_t addr) {
    asm volatile("ldmatrix.sync.aligned.m8n8.x4.trans.shared.b16 {%0,%1,%2,%3}, [%4];"
                 : "=r"(r0), "=r"(r1), "=r"(r2), "=r"(r3) : "r"(addr));
}
__device__ __forceinline__ uint32_t scale_pack(const __half* p, float s) {
    float2 f = __half22float2(*(const __half2*)p);
    __half2 h = __floats2half2_rn(f.x * s, f.y * s);
    return *(uint32_t*)&h;
}

// ---------------------------------------------------------------------------
// Prepass kernels
// ---------------------------------------------------------------------------
__global__ void to_half(const float* __restrict__ src, __half* __restrict__ dst, int n4)
{
    int i = blockIdx.x * blockDim.x + threadIdx.x;
    if (i < n4) {
        float4 v = ((const float4*)src)[i];
        __half2* d2 = (__half2*)dst + i * 2;
        d2[0] = __floats2half2_rn(v.x, v.y);
        d2[1] = __floats2half2_rn(v.z, v.w);
    }
}

__global__ void transpose_half(const float* __restrict__ src, __half* __restrict__ dst,
                               int K, int N)
{
    __shared__ float t[32][33];
    int nb = blockIdx.x * 32, kb = blockIdx.y * 32;
    int tx = threadIdx.x, ty = threadIdx.y;
    #pragma unroll
    for (int i = 0; i < 4; ++i)
        t[ty + i * 8][tx] = src[(size_t)(kb + ty + i * 8) * N + nb + tx];
    __syncthreads();
    #pragma unroll
    for (int i = 0; i < 4; ++i)
        dst[(size_t)(nb + ty + i * 8) * K + kb + tx] = __float2half(t[tx][ty + i * 8]);
}

// ---------------------------------------------------------------------------
// FP16 GEMM (R14/R15, proven): C = A[M,K] @ BT[N,K]^T, fp32 accum, ldmatrix.
// ---------------------------------------------------------------------------
#define BM 128
#define BN 128
#define BKH 64
#define BKP 72

#define SMEM_AB_HALFS (BM * BKP)
#define SMEM_STAGE_H  (2 * SMEM_AB_HALFS)
#define GEMM_SMEM_BYTES (2 * SMEM_STAGE_H * 2)      // 73,728 B

template<bool OUT_HALF>
__global__ __launch_bounds__(256, 2)
void gemm_fp16(const __half* __restrict__ A, const __half* __restrict__ BT,
               void* __restrict__ Cv, int M, int N, int K)
{
    extern __shared__ __half smh[];

    const int tid  = threadIdx.x;
    const int lane = tid & 31;
    const int warp = tid >> 5;
    const int g    = lane >> 2;
    const int tig  = lane & 3;
    const int Wm   = (warp >> 1) * 32;
    const int Wn   = (warp & 1) * 64;
    const int brow = blockIdx.y * BM;
    const int bcol = blockIdx.x * BN;

    const int arow = ((lane >> 3) & 1) * 8 + (lane & 7);
    const int acol = ((lane >> 4) & 1) * 8;
    const int brw  = ((lane >> 4) & 1) * 8 + (lane & 7);
    const int bcl  = ((lane >> 3) & 1) * 8;

    const uint32_t smem_base_u32 = (uint32_t)__cvta_generic_to_shared(smh);
    const uint32_t aoff = ((Wm + arow) * BKP + acol) * 2;
    const uint32_t boff = (SMEM_AB_HALFS + (Wn + brw) * BKP + bcl) * 2;

    float acc[2][8][4];
    #pragma unroll
    for (int mt = 0; mt < 2; ++mt)
        #pragma unroll
        for (int nt = 0; nt < 8; ++nt)
            #pragma unroll
            for (int j = 0; j < 4; ++j) acc[mt][nt][j] = 0.0f;

    auto load_tile = [&](int k0, int buf) {
        __half* a_s = smh + buf * SMEM_STAGE_H;
        __half* b_s = a_s + SMEM_AB_HALFS;
        #pragma unroll
        for (int q = 0; q < 4; ++q) {
            int idx = tid + q * 256;
            int r = idx >> 3;
            int j = idx & 7;
            cp_async16(a_s + r * BKP + j * 8, A + (size_t)(brow + r) * K + k0 + j * 8);
        }
        #pragma unroll
        for (int q = 0; q < 4; ++q) {
            int idx = tid + q * 256;
            int r = idx >> 3;
            int j = idx & 7;
            cp_async16(b_s + r * BKP + j * 8, BT + (size_t)(bcol + r) * K + k0 + j * 8);
        }
        asm volatile("cp.async.commit_group;\n");
    };

    const int nIter = K / BKH;
    load_tile(0, 0);

    for (int it = 0; it < nIter; ++it) {
        if (it + 1 < nIter) {
            load_tile((it + 1) * BKH, (it + 1) & 1);
            asm volatile("cp.async.wait_group 1;\n");
        } else {
            asm volatile("cp.async.wait_group 0;\n");
        }
        __syncthreads();

        const uint32_t stage = smem_base_u32 + (uint32_t)((it & 1) * SMEM_STAGE_H * 2);
        const uint32_t abase = stage + aoff;
        const uint32_t bbase = stage + boff;

        #pragma unroll
        for (int ks = 0; ks < 4; ++ks) {
            uint32_t af[2][4];
            #pragma unroll
            for (int mt = 0; mt < 2; ++mt)
                ldmx4(af[mt][0], af[mt][1], af[mt][2], af[mt][3],
                      abase + (uint32_t)(mt * 16 * BKP * 2 + ks * 32));
            #pragma unroll
            for (int nt2 = 0; nt2 < 4; ++nt2) {
                uint32_t b0, b1, b2, b3;
                ldmx4(b0, b1, b2, b3,
                      bbase + (uint32_t)(nt2 * 16 * BKP * 2 + ks * 32));
                uint32_t vb0[2] = {b0, b1};
                uint32_t vb1[2] = {b2, b3};
                #pragma unroll
                for (int mt = 0; mt < 2; ++mt) {
                    mma_fp16(acc[mt][2 * nt2],     af[mt], vb0);
                    mma_fp16(acc[mt][2 * nt2 + 1], af[mt], vb1);
                }
            }
        }
        __syncthreads();
    }

    #pragma unroll
    for (int mt = 0; mt < 2; ++mt) {
        int row = brow + Wm + mt * 16 + g;
        #pragma unroll
        for (int nt = 0; nt < 8; ++nt) {
            int col = bcol + Wn + nt * 8 + tig * 2;
            if (OUT_HALF) {
                __half* C = (__half*)Cv;
                *(__half2*)(C + (size_t)row * N + col) =
                    __floats2half2_rn(acc[mt][nt][0], acc[mt][nt][1]);
                *(__half2*)(C + (size_t)(row + 8) * N + col) =
                    __floats2half2_rn(acc[mt][nt][2], acc[mt][nt][3]);
            } else {
                float* C = (float*)Cv;
                *(float2*)(C + (size_t)row * N + col) =
                    make_float2(acc[mt][nt][0], acc[mt][nt][1]);
                *(float2*)(C + (size_t)(row + 8) * N + col) =
                    make_float2(acc[mt][nt][2], acc[mt][nt][3]);
            }
        }
    }
}

// ---------------------------------------------------------------------------
// FP16 flash attention (causal), R16: all fragment traffic via ldmatrix.
//   QK^T: non-trans ldmatrix on K tile (GEMM B-frag pattern).
//   PV:   trans ldmatrix directly on V tile (no smem transpose, one fewer
//         barrier per kt-tile); P A-frags via non-trans ldmatrix.
// ---------------------------------------------------------------------------
#define ABQ 128
#define ABK 64
#define KPH 136
#define VPH 136
#define PPH 72
#define QPH 136

#define STAGE_H   (ABK * KPH + ABK * VPH)            // 17408 halfs
#define STAGE_B   (STAGE_H * 2)                      // 34816 B
#define PS_OFF    (2 * STAGE_B)                      // 69632
#define ATTN_SMEM_BYTES (PS_OFF + ABQ * PPH * 2)     // 88,064 B

__global__ __launch_bounds__(256, 1)
void attn_fp16(const __half* __restrict__ qkv, __half* __restrict__ yh)
{
    extern __shared__ char smc[];
    __half* Ps = (__half*)(smc + PS_OFF);

    const int tid  = threadIdx.x;
    const int lane = tid & 31;
    const int warp = tid >> 5;
    const int g    = lane >> 2;
    const int tig  = lane & 3;
    const int qt   = (int)gridDim.x - 1 - (int)blockIdx.x;
    const int h    = blockIdx.y;
    const int b    = blockIdx.z;

    const size_t base  = (size_t)b * SEQ * QKVDIM + (size_t)h * HD;
    const float  scale = 0.08838834764831845f;
    const int    r0    = warp * 16;

    // per-lane ldmatrix address components
    const int l8   = lane & 7;
    const int h3   = (lane >> 3) & 1;
    const int h4   = (lane >> 4) & 1;
    // K (non-trans B-frag): key = 16j + h4*8 + l8, d = 16ks + h3*8
    const uint32_t k_lane_off = (uint32_t)(((h4 * 8 + l8) * KPH + h3 * 8) * 2);
    // V (trans B-frag): key = 16ks2 + h3*8 + l8, d = 16j + h4*8
    const uint32_t v_lane_off = (uint32_t)(((h3 * 8 + l8) * VPH + h4 * 8) * 2);
    // P (non-trans A-frag): row = r0 + h3*8 + l8, col = 16ks2 + h4*8
    const uint32_t smem_u32 = (uint32_t)__cvta_generic_to_shared(smc);
    const uint32_t ps_u32   = smem_u32 + PS_OFF;
    const uint32_t p_lane   = ps_u32 + (uint32_t)(((r0 + h3 * 8 + l8) * PPH + h4 * 8) * 2);

    // ---- Stage Q tile (fp16), build pre-scaled A-frags in regs
    uint32_t qf[8][4];
    {
        __half* Qst = (__half*)smc;
        #pragma unroll
        for (int q = 0; q < 8; ++q) {
            int i = tid + q * 256;
            int r = i >> 4, j = i & 15;
            *(uint4*)(Qst + (size_t)r * QPH + j * 8) =
                *(const uint4*)(qkv + base + (size_t)(qt * ABQ + r) * QKVDIM + j * 8);
        }
        __syncthreads();
        #pragma unroll
        for (int ks = 0; ks < 8; ++ks) {
            const __half* p = Qst + (size_t)(r0 + g) * QPH + ks * 16 + 2 * tig;
            qf[ks][0] = scale_pack(p, scale);
            qf[ks][1] = scale_pack(p + 8 * QPH, scale);
            qf[ks][2] = scale_pack(p + 8, scale);
            qf[ks][3] = scale_pack(p + 8 * QPH + 8, scale);
        }
        __syncthreads();
    }

    float of[16][4];
    #pragma unroll
    for (int nb = 0; nb < 16; ++nb)
        #pragma unroll
        for (int j = 0; j < 4; ++j) of[nb][j] = 0.0f;

    float m0 = -1e30f, m1 = -1e30f, l0 = 0.0f, l1 = 0.0f;
    const int rowg0  = qt * ABQ + r0 + g;
    const int rowg1  = rowg0 + 8;
    const int rowmax = qt * ABQ + r0 + 15;
    const int ktmax  = 2 * qt + 1;

    auto load_kv = [&](int kt, int buf) {
        __half* Kd = (__half*)(smc + buf * STAGE_B);
        __half* Vd = Kd + ABK * KPH;
        #pragma unroll
        for (int q = 0; q < 4; ++q) {
            int i = tid + q * 256;
            int r = i >> 4, j = i & 15;
            size_t tok = (size_t)(kt * ABK + r) * QKVDIM;
            cp_async16(Kd + (size_t)r * KPH + j * 8, qkv + base + CDIM     + tok + j * 8);
            cp_async16(Vd + (size_t)r * VPH + j * 8, qkv + base + 2 * CDIM + tok + j * 8);
        }
        asm volatile("cp.async.commit_group;\n");
    };

    load_kv(0, 0);

    for (int kt = 0; kt <= ktmax; ++kt) {
        if (kt + 1 <= ktmax) {
            load_kv(kt + 1, (kt + 1) & 1);
            asm volatile("cp.async.wait_group 1;\n");
        } else {
            asm volatile("cp.async.wait_group 0;\n");
        }
        __syncthreads();

        const uint32_t ks_u32 = smem_u32 + (uint32_t)((kt & 1) * STAGE_B);
        const uint32_t vs_u32 = ks_u32 + (uint32_t)(ABK * KPH * 2);

        const int colbase = kt * ABK;
        const bool skip = colbase > rowmax;

        if (!skip) {
            // ---- S = Q K^T : per ks, 4 ldmatrix (each covers 2 key-blocks)
            float sf[8][4];
            #pragma unroll
            for (int nb = 0; nb < 8; ++nb)
                #pragma unroll
                for (int j = 0; j < 4; ++j) sf[nb][j] = 0.0f;

            const uint32_t kbase = ks_u32 + k_lane_off;
            #pragma unroll
            for (int ks = 0; ks < 8; ++ks) {
                #pragma unroll
                for (int j = 0; j < 4; ++j) {
                    uint32_t b0, b1, b2, b3;
                    ldmx4(b0, b1, b2, b3,
                          kbase + (uint32_t)(16 * j * KPH * 2 + ks * 32));
                    uint32_t vb0[2] = {b0, b1};
                    uint32_t vb1[2] = {b2, b3};
                    mma_fp16(sf[2 * j],     qf[ks], vb0);
                    mma_fp16(sf[2 * j + 1], qf[ks], vb1);
                }
            }

            // ---- causal mask
            if (colbase + ABK - 1 > rowg0) {
                #pragma unroll
                for (int nb = 0; nb < 8; ++nb) {
                    int col = colbase + nb * 8 + 2 * tig;
                    if (col     > rowg0) sf[nb][0] = -1e30f;
                    if (col + 1 > rowg0) sf[nb][1] = -1e30f;
                    if (col     > rowg1) sf[nb][2] = -1e30f;
                    if (col + 1 > rowg1) sf[nb][3] = -1e30f;
                }
            }

            // ---- online softmax (fp32)
            float mx0 = -1e30f, mx1 = -1e30f;
            #pragma unroll
            for (int nb = 0; nb < 8; ++nb) {
                mx0 = fmaxf(mx0, fmaxf(sf[nb][0], sf[nb][1]));
                mx1 = fmaxf(mx1, fmaxf(sf[nb][2], sf[nb][3]));
            }
            mx0 = fmaxf(mx0, __shfl_xor_sync(0xffffffffu, mx0, 1));
            mx0 = fmaxf(mx0, __shfl_xor_sync(0xffffffffu, mx0, 2));
            mx1 = fmaxf(mx1, __shfl_xor_sync(0xffffffffu, mx1, 1));
            mx1 = fmaxf(mx1, __shfl_xor_sync(0xffffffffu, mx1, 2));

            float nm0 = fmaxf(m0, mx0);
            float nm1 = fmaxf(m1, mx1);
            float cr0 = __expf(m0 - nm0);
            float cr1 = __expf(m1 - nm1);

            float rs0 = 0.0f, rs1 = 0.0f;
            #pragma unroll
            for (int nb = 0; nb < 8; ++nb) {
                float e0 = __expf(sf[nb][0] - nm0);
                float e1 = __expf(sf[nb][1] - nm0);
                float e2 = __expf(sf[nb][2] - nm1);
                float e3 = __expf(sf[nb][3] - nm1);
                rs0 += e0 + e1;
                rs1 += e2 + e3;
                *(__half2*)(Ps + (size_t)(r0 + g)     * PPH + nb * 8 + 2 * tig) =
                    __floats2half2_rn(e0, e1);
                *(__half2*)(Ps + (size_t)(r0 + g + 8) * PPH + nb * 8 + 2 * tig) =
                    __floats2half2_rn(e2, e3);
            }
            rs0 += __shfl_xor_sync(0xffffffffu, rs0, 1);
            rs0 += __shfl_xor_sync(0xffffffffu, rs0, 2);
            rs1 += __shfl_xor_sync(0xffffffffu, rs1, 1);
            rs1 += __shfl_xor_sync(0xffffffffu, rs1, 2);

            m0 = nm0; m1 = nm1;
            l0 = l0 * cr0 + rs0;
            l1 = l1 * cr1 + rs1;

            #pragma unroll
            for (int nb = 0; nb < 16; ++nb) {
                of[nb][0] *= cr0; of[nb][1] *= cr0;
                of[nb][2] *= cr1; of[nb][3] *= cr1;
            }
            __syncwarp();   // P stores visible to this warp's ldmatrix

            // ---- O += P V : P via ldmatrix (A-frag), V via trans ldmatrix
            const uint32_t vbase = vs_u32 + v_lane_off;
            #pragma unroll
            for (int ks2 = 0; ks2 < 4; ++ks2) {
                uint32_t pa[4];
                ldmx4(pa[0], pa[1], pa[2], pa[3], p_lane + (uint32_t)(ks2 * 32));
                #pragma unroll
                for (int j = 0; j < 8; ++j) {
                    uint32_t b0, b1, b2, b3;
                    ldmx4t(b0, b1, b2, b3,
                           vbase + (uint32_t)(ks2 * 16 * VPH * 2 + j * 32));
                    uint32_t vb0[2] = {b0, b1};
                    uint32_t vb1[2] = {b2, b3};
                    mma_fp16(of[2 * j],     pa, vb0);
                    mma_fp16(of[2 * j + 1], pa, vb1);
                }
            }
            __syncwarp();
        }
        __syncthreads();   // stage reuse guard
    }

    // ---- normalize, write yh (fp16)
    float inv0 = 1.0f / l0;
    float inv1 = 1.0f / l1;
    size_t yrow0 = (size_t)b * SEQ + rowg0;
    size_t yrow1 = (size_t)b * SEQ + rowg1;
    #pragma unroll
    for (int nb = 0; nb < 16; ++nb) {
        int col = h * HD + nb * 8 + 2 * tig;
        *(__half2*)(yh + yrow0 * CDIM + col) =
            __floats2half2_rn(of[nb][0] * inv0, of[nb][1] * inv0);
        *(__half2*)(yh + yrow1 * CDIM + col) =
            __floats2half2_rn(of[nb][2] * inv1, of[nb][3] * inv1);
    }
}

// ---------------------------------------------------------------------------
// kernel_launch
// ---------------------------------------------------------------------------
extern "C" void kernel_launch(void* const* d_in, const int* in_sizes, int n_in,
                              void* d_out, int out_size)
{
    const float* x     = (const float*)d_in[0];
    const float* Wqkv  = (const float*)d_in[1];
    const float* Wproj = (const float*)d_in[2];
    float* out = (float*)d_out;

    __half *qkv, *yh, *xh, *wqkvT, *wprjT;
    cudaGetSymbolAddress((void**)&qkv,   g_qkv);
    cudaGetSymbolAddress((void**)&yh,    g_yh);
    cudaGetSymbolAddress((void**)&xh,    g_xh);
    cudaGetSymbolAddress((void**)&wqkvT, g_wqkvT);
    cudaGetSymbolAddress((void**)&wprjT, g_wprjT);

    cudaFuncSetAttribute(gemm_fp16<true>,
                         cudaFuncAttributeMaxDynamicSharedMemorySize, GEMM_SMEM_BYTES);
    cudaFuncSetAttribute(gemm_fp16<false>,
                         cudaFuncAttributeMaxDynamicSharedMemorySize, GEMM_SMEM_BYTES);
    cudaFuncSetAttribute(attn_fp16,
                         cudaFuncAttributeMaxDynamicSharedMemorySize, ATTN_SMEM_BYTES);

    // 0) inputs -> fp16 (weights transposed to [N][K])
    {
        int n4x = MROWS * CDIM / 4;
        to_half<<<(n4x + 255) / 256, 256>>>(x, xh, n4x);
        transpose_half<<<dim3(QKVDIM / 32, CDIM / 32), dim3(32, 8)>>>(Wqkv,  wqkvT, CDIM, QKVDIM);
        transpose_half<<<dim3(CDIM / 32,  CDIM / 32), dim3(32, 8)>>>(Wproj, wprjT, CDIM, CDIM);
    }

    // 1) qkv = x @ Wqkv  (fp16 out)
    gemm_fp16<true><<<dim3(QKVDIM / BN, MROWS / BM), 256, GEMM_SMEM_BYTES>>>(
        xh, wqkvT, qkv, MROWS, QKVDIM, CDIM);

    // 2) attention (fp16 mma, ldmatrix) -> yh
    attn_fp16<<<dim3(SEQ / ABQ, NHEAD, BATCH), 256, ATTN_SMEM_BYTES>>>(qkv, yh);

    // 3) out = yh @ Wproj (fp32 out)
    gemm_fp16<false><<<dim3(CDIM / BN, MROWS / BM), 256, GEMM_SMEM_BYTES>>>(
        yh, wprjT, out, MROWS, CDIM, CDIM);
}